// round 8
// baseline (speedup 1.0000x reference)
#include <cuda_runtime.h>
#include <cuda_bf16.h>
#include <stdint.h>
#include <math.h>

#define BB   8
#define SS   2048
#define HH   256
#define NHH  4
#define HDD  64
#define MTOT (BB * SS)   // 16384

// ---------------------------------------------------------------------------
// Scratch (__device__ globals only).
// ---------------------------------------------------------------------------
__device__ __align__(128) __nv_bfloat16 g_Qb[32 * SS * HDD];   // [bh][s][d]
__device__ __align__(128) __nv_bfloat16 g_Kb[32 * SS * HDD];   // [bh][s][d]
__device__ __align__(128) __nv_bfloat16 g_Vt[32 * HDD * SS];   // [bh][d][s] (transposed)
__device__ __align__(128) __nv_bfloat16 g_ctxb[MTOT * HH];     // [m][h*64+d]
__device__ __align__(128) float         g_resid[MTOT * HH];

// ---------------------------------------------------------------------------
// Helpers
// ---------------------------------------------------------------------------
__device__ __forceinline__ uint32_t packbf(float lo, float hi) {
    uint32_t r;
    asm("cvt.rn.bf16x2.f32 %0, %1, %2;" : "=r"(r) : "f"(hi), "f"(lo));
    return r;
}

__device__ __forceinline__ void mma16816(float* c, const uint32_t* a, const uint32_t* b) {
    asm volatile(
        "mma.sync.aligned.m16n8k16.row.col.f32.bf16.bf16.f32 "
        "{%0,%1,%2,%3}, {%4,%5,%6,%7}, {%8,%9}, {%0,%1,%2,%3};\n"
        : "+f"(c[0]), "+f"(c[1]), "+f"(c[2]), "+f"(c[3])
        : "r"(a[0]), "r"(a[1]), "r"(a[2]), "r"(a[3]), "r"(b[0]), "r"(b[1]));
}

__device__ __forceinline__ uint32_t smem_u32(const void* p) {
    uint32_t a;
    asm("{ .reg .u64 t; cvta.to.shared.u64 t, %1; cvt.u32.u64 %0, t; }" : "=r"(a) : "l"(p));
    return a;
}

__device__ __forceinline__ void ldsm4(uint32_t& r0, uint32_t& r1, uint32_t& r2, uint32_t& r3,
                                      uint32_t addr) {
    asm volatile("ldmatrix.sync.aligned.m8n8.x4.shared.b16 {%0,%1,%2,%3}, [%4];"
                 : "=r"(r0), "=r"(r1), "=r"(r2), "=r"(r3) : "r"(addr));
}

__device__ __forceinline__ void cp16(uint32_t dst, const void* src) {
    asm volatile("cp.async.cg.shared.global [%0], [%1], 16;" :: "r"(dst), "l"(src));
}
#define CP_COMMIT() asm volatile("cp.async.commit_group;" ::: "memory")
#define CP_WAIT1()  asm volatile("cp.async.wait_group 1;" ::: "memory")
#define CP_WAIT0()  asm volatile("cp.async.wait_group 0;" ::: "memory")

#define GP 40   // smem pitch for mma.sync GEMM tiles (qkv/proj)

// ---------------------------------------------------------------------------
// Kernel 1: QKV projection (bf16 mma.sync, unchanged).
// Q,K split-head row-major; V transposed [bh][d][s].
// ---------------------------------------------------------------------------
__global__ __launch_bounds__(128) void qkv_kernel(
    const float* __restrict__ X,
    const float* __restrict__ Wq, const float* __restrict__ bq,
    const float* __restrict__ Wk, const float* __restrict__ bk,
    const float* __restrict__ Wv, const float* __restrict__ bv)
{
    __shared__ __nv_bfloat16 As[128 * GP];
    __shared__ __nv_bfloat16 Bs[64 * GP];

    const int z = blockIdx.z;
    const float* W;  const float* bias;
    if (z == 0)      { W = Wq; bias = bq; }
    else if (z == 1) { W = Wk; bias = bk; }
    else             { W = Wv; bias = bv; }

    const int t = threadIdx.x;
    const int w = t >> 5, lane = t & 31;
    const int g = lane >> 2, tig = lane & 3;
    const int m0 = blockIdx.y * 128, n0 = blockIdx.x * 64;

    float c[2][8][4];
    #pragma unroll
    for (int mt = 0; mt < 2; mt++)
        #pragma unroll
        for (int j = 0; j < 8; j++)
            #pragma unroll
            for (int i = 0; i < 4; i++) c[mt][j][i] = 0.0f;

    for (int k0 = 0; k0 < HH; k0 += 32) {
        #pragma unroll
        for (int i = 0; i < 8; i++) {
            int m = (t >> 3) + 16 * i;
            int k = 4 * (t & 7);
            float4 v = *(const float4*)(X + (m0 + m) * HH + k0 + k);
            uint2 p;
            p.x = packbf(v.x, v.y);
            p.y = packbf(v.z, v.w);
            *(uint2*)&As[m * GP + k] = p;
        }
        #pragma unroll
        for (int i = 0; i < 8; i++) {
            int idx = 2 * t + 256 * i;
            int k = idx >> 6, n = idx & 63;
            float2 v = *(const float2*)(W + (k0 + k) * HH + n0 + n);
            Bs[n * GP + k]       = __float2bfloat16(v.x);
            Bs[(n + 1) * GP + k] = __float2bfloat16(v.y);
        }
        __syncthreads();

        uint32_t a[2][2][4];
        #pragma unroll
        for (int mt = 0; mt < 2; mt++)
            #pragma unroll
            for (int kt = 0; kt < 2; kt++) {
                int r = w * 32 + mt * 16;
                a[mt][kt][0] = *(const uint32_t*)&As[(r + g)     * GP + kt * 16 + 2 * tig];
                a[mt][kt][1] = *(const uint32_t*)&As[(r + g + 8) * GP + kt * 16 + 2 * tig];
                a[mt][kt][2] = *(const uint32_t*)&As[(r + g)     * GP + kt * 16 + 2 * tig + 8];
                a[mt][kt][3] = *(const uint32_t*)&As[(r + g + 8) * GP + kt * 16 + 2 * tig + 8];
            }
        #pragma unroll
        for (int j = 0; j < 8; j++) {
            #pragma unroll
            for (int kt = 0; kt < 2; kt++) {
                uint32_t b[2];
                b[0] = *(const uint32_t*)&Bs[(8 * j + g) * GP + kt * 16 + 2 * tig];
                b[1] = *(const uint32_t*)&Bs[(8 * j + g) * GP + kt * 16 + 2 * tig + 8];
                mma16816(c[0][j], a[0][kt], b);
                mma16816(c[1][j], a[1][kt], b);
            }
        }
        __syncthreads();
    }

    const int head = blockIdx.x;
    #pragma unroll
    for (int mt = 0; mt < 2; mt++) {
        int r0 = m0 + w * 32 + mt * 16 + g;
        #pragma unroll
        for (int half = 0; half < 2; half++) {
            int m  = r0 + half * 8;
            int b_ = m >> 11;
            int s_ = m & (SS - 1);
            int bh = b_ * NHH + head;
            #pragma unroll
            for (int j = 0; j < 8; j++) {
                int d = 8 * j + 2 * tig;
                float v0 = c[mt][j][half * 2 + 0] + bias[n0 + d];
                float v1 = c[mt][j][half * 2 + 1] + bias[n0 + d + 1];
                if (z == 0) {
                    *(uint32_t*)&g_Qb[(bh * SS + s_) * HDD + d] = packbf(v0, v1);
                } else if (z == 1) {
                    *(uint32_t*)&g_Kb[(bh * SS + s_) * HDD + d] = packbf(v0, v1);
                } else {
                    g_Vt[(bh * HDD + d)     * SS + s_] = __float2bfloat16(v0);
                    g_Vt[(bh * HDD + d + 1) * SS + s_] = __float2bfloat16(v1);
                }
            }
        }
    }
}

// ---------------------------------------------------------------------------
// Kernel 2: flash attention, 256 threads / 8 warps, 16 q-rows per warp.
// BQ=128, BK=64, 2-buffer K/V/mask cp.async pipeline (wait_group 1).
// Dynamic smem (102400 B): K0@0 K1@8192 V0@16384 V1@24576 (64x128B swizzled),
// M0@32768 M1@67584 (128 rows x 68 floats).
// ---------------------------------------------------------------------------
#define NIT 32            // SS / 64
#define SM_K0   0
#define SM_K1   8192
#define SM_V0   16384
#define SM_V1   24576
#define SM_M0   32768
#define SM_M1   67584
#define MPITCH  68        // floats per mask row (272 B, 16B-aligned)
#define ATTN_SMEM 102400

__global__ __launch_bounds__(256) void attn_kernel(const float* __restrict__ mask)
{
    extern __shared__ char dynsm[];

    const int t = threadIdx.x;
    const int w = t >> 5, lane = t & 31;
    const int g = lane >> 2, tig = lane & 3;
    const int bh = blockIdx.x;
    const int qb = blockIdx.y;
    const int b_ = bh >> 2;
    const int h_ = bh & 3;

    const uint32_t smb = smem_u32(dynsm);
    const uint32_t kbase[2] = { smb + SM_K0, smb + SM_K1 };
    const uint32_t vbase[2] = { smb + SM_V0, smb + SM_V1 };
    const uint32_t mbase[2] = { smb + SM_M0, smb + SM_M1 };
    float* const msm[2] = { (float*)(dynsm + SM_M0), (float*)(dynsm + SM_M1) };

    const __nv_bfloat16* Qg = g_Qb + (size_t)bh * SS * HDD;
    const char* Kg = (const char*)(g_Kb + (size_t)bh * SS * HDD);
    const char* Vg = (const char*)(g_Vt + (size_t)bh * HDD * SS);
    const float* Mb = mask + (size_t)b_ * SS * SS + (size_t)(qb * 128) * SS;

    // K/V cp.async chunks: c = t + 256*jc (jc<2) -> row (0..63), seg (0..7)
    int ld_dst[2], ld_row[2];
    #pragma unroll
    for (int jc = 0; jc < 2; jc++) {
        int c = t + 256 * jc;
        int row = c >> 3, seg = c & 7;
        ld_row[jc] = row;
        ld_dst[jc] = row * 128 + ((seg * 16) ^ ((row & 7) * 16));
    }
    // Mask chunks: c = t + 256*jm (jm<8) -> row (0..127), seg (0..15)
    int md_dst[8], md_row[8];
    #pragma unroll
    for (int jm = 0; jm < 8; jm++) {
        int c = t + 256 * jm;
        int row = c >> 4, seg = c & 15;
        md_row[jm] = row;
        md_dst[jm] = row * (MPITCH * 4) + seg * 16;
    }

    // ldmatrix addressing (B-frags for both S and PV loops)
    const int lrow = (lane & 7) | ((lane & 16) >> 1);
    const int lkb  = (lane & 8) ? 16 : 0;
    const int lxor = (lrow & 7) * 16;
    const int lbase = lrow * 128;

    // Q A-fragments: one 16-row m-tile per warp, resident all iterations
    const int qrow = qb * 128 + w * 16 + g;
    uint32_t aq[4][4];
    {
        const __nv_bfloat16* r0 = Qg + (size_t)qrow * HDD;
        const __nv_bfloat16* r1 = r0 + 8 * HDD;
        #pragma unroll
        for (int kt = 0; kt < 4; kt++) {
            aq[kt][0] = *(const uint32_t*)(r0 + kt * 16 + 2 * tig);
            aq[kt][1] = *(const uint32_t*)(r1 + kt * 16 + 2 * tig);
            aq[kt][2] = *(const uint32_t*)(r0 + kt * 16 + 2 * tig + 8);
            aq[kt][3] = *(const uint32_t*)(r1 + kt * 16 + 2 * tig + 8);
        }
    }

    // tile loader: K tile [kv][d], V tile [d][kv], mask tile 128x64
    auto load_tiles = [&](int it, int buf) {
        const char* Ks = Kg + (size_t)it * 64 * 128;
        #pragma unroll
        for (int jc = 0; jc < 2; jc++) {
            cp16(kbase[buf] + ld_dst[jc], Ks + (size_t)ld_row[jc] * 128 + (t & 7) * 16);
            cp16(vbase[buf] + ld_dst[jc],
                 Vg + (size_t)ld_row[jc] * (SS * 2) + it * 128 + (t & 7) * 16);
        }
        #pragma unroll
        for (int jm = 0; jm < 8; jm++) {
            cp16(mbase[buf] + md_dst[jm],
                 (const char*)(Mb + (size_t)md_row[jm] * SS + it * 64) + (t & 15) * 16);
        }
        CP_COMMIT();
    };

    // prologue: tiles 0 and 1
    load_tiles(0, 0);
    load_tiles(1, 1);

    float o[8][4];
    #pragma unroll
    for (int j = 0; j < 8; j++)
        #pragma unroll
        for (int i = 0; i < 4; i++) o[j][i] = 0.0f;
    float lacc[2] = {0.0f, 0.0f};

    for (int i = 0; i < NIT; i++) {
        const int buf = i & 1;
        if (i < NIT - 1) { CP_WAIT1(); } else { CP_WAIT0(); }
        __syncthreads();

        // ---- S = Q @ K^T (16 x 64 per warp) ----
        float c[8][4];
        #pragma unroll
        for (int j = 0; j < 8; j++)
            #pragma unroll
            for (int q = 0; q < 4; q++) c[j][q] = 0.0f;

        #pragma unroll
        for (int jj = 0; jj < 4; jj++) {
            #pragma unroll
            for (int kt = 0; kt < 4; kt++) {
                uint32_t r0, r1, r2, r3;
                ldsm4(r0, r1, r2, r3,
                      kbase[buf] + jj * 2048 + lbase + ((kt * 32 + lkb) ^ lxor));
                uint32_t blo[2] = { r0, r1 }, bhi[2] = { r2, r3 };
                mma16816(c[2 * jj],     aq[kt], blo);
                mma16816(c[2 * jj + 1], aq[kt], bhi);
            }
        }

        // ---- softmax (no max): p = exp(s/8 + mask), mask from SMEM ----
        uint32_t pa[4][4];
        {
            const float* mp0 = msm[buf] + (w * 16 + g) * MPITCH + 2 * tig;
            const float* mp1 = mp0 + 8 * MPITCH;
            #pragma unroll
            for (int j = 0; j < 8; j++) {
                float2 mk0 = *(const float2*)(mp0 + 8 * j);
                float2 mk1 = *(const float2*)(mp1 + 8 * j);
                float p0 = __expf(fmaf(c[j][0], 0.125f, mk0.x));
                float p1 = __expf(fmaf(c[j][1], 0.125f, mk0.y));
                float p2 = __expf(fmaf(c[j][2], 0.125f, mk1.x));
                float p3 = __expf(fmaf(c[j][3], 0.125f, mk1.y));
                lacc[0] += p0 + p1;
                lacc[1] += p2 + p3;
                int kt = j >> 1, hi = (j & 1) * 2;
                pa[kt][hi + 0] = packbf(p0, p1);
                pa[kt][hi + 1] = packbf(p2, p3);
            }
        }

        // ---- O += P @ V (V tile is [d][kv], non-trans ldmatrix) ----
        #pragma unroll
        for (int jj = 0; jj < 4; jj++) {
            #pragma unroll
            for (int kt = 0; kt < 4; kt++) {
                uint32_t r0, r1, r2, r3;
                ldsm4(r0, r1, r2, r3,
                      vbase[buf] + jj * 2048 + lbase + ((kt * 32 + lkb) ^ lxor));
                uint32_t blo[2] = { r0, r1 }, bhi[2] = { r2, r3 };
                mma16816(o[2 * jj],     pa[kt], blo);
                mma16816(o[2 * jj + 1], pa[kt], bhi);
            }
        }

        __syncthreads();   // everyone done reading buf before it is overwritten

        if (i + 2 < NIT) load_tiles(i + 2, buf);
    }

    // ---- final: reduce l across the 4 lanes of each row group, write ctx ----
    #pragma unroll
    for (int h = 0; h < 2; h++) {
        float v = lacc[h];
        v += __shfl_xor_sync(0xffffffffu, v, 1);
        v += __shfl_xor_sync(0xffffffffu, v, 2);
        lacc[h] = 1.0f / v;
    }

    {
        __nv_bfloat16* c0 = g_ctxb + ((size_t)b_ * SS + qrow) * HH + h_ * HDD;
        __nv_bfloat16* c1 = c0 + 8 * HH;
        #pragma unroll
        for (int j = 0; j < 8; j++) {
            int d = 8 * j + 2 * tig;
            *(uint32_t*)(c0 + d) = packbf(o[j][0] * lacc[0], o[j][1] * lacc[0]);
            *(uint32_t*)(c1 + d) = packbf(o[j][2] * lacc[1], o[j][3] * lacc[1]);
        }
    }
}

// ---------------------------------------------------------------------------
// Kernel 3: out projection + residual (bf16 mma.sync, unchanged)
// ---------------------------------------------------------------------------
__global__ __launch_bounds__(128) void proj_kernel(
    const float* __restrict__ X,
    const float* __restrict__ Wo, const float* __restrict__ bo)
{
    __shared__ __nv_bfloat16 As[128 * GP];
    __shared__ __nv_bfloat16 Bs[64 * GP];

    const int t = threadIdx.x;
    const int w = t >> 5, lane = t & 31;
    const int g = lane >> 2, tig = lane & 3;
    const int m0 = blockIdx.y * 128, n0 = blockIdx.x * 64;

    float c[2][8][4];
    #pragma unroll
    for (int mt = 0; mt < 2; mt++)
        #pragma unroll
        for (int j = 0; j < 8; j++)
            #pragma unroll
            for (int i = 0; i < 4; i++) c[mt][j][i] = 0.0f;

    for (int k0 = 0; k0 < HH; k0 += 32) {
        #pragma unroll
        for (int i = 0; i < 4; i++) {
            int m = (t >> 2) + 32 * i;
            int k = 8 * (t & 3);
            *(uint4*)&As[m * GP + k] =
                *(const uint4*)&g_ctxb[(m0 + m) * HH + k0 + k];
        }
        #pragma unroll
        for (int i = 0; i < 8; i++) {
            int idx = 2 * t + 256 * i;
            int k = idx >> 6, n = idx & 63;
            float2 v = *(const float2*)(Wo + (k0 + k) * HH + n0 + n);
            Bs[n * GP + k]       = __float2bfloat16(v.x);
            Bs[(n + 1) * GP + k] = __float2bfloat16(v.y);
        }
        __syncthreads();

        uint32_t a[2][2][4];
        #pragma unroll
        for (int mt = 0; mt < 2; mt++)
            #pragma unroll
            for (int kt = 0; kt < 2; kt++) {
                int r = w * 32 + mt * 16;
                a[mt][kt][0] = *(const uint32_t*)&As[(r + g)     * GP + kt * 16 + 2 * tig];
                a[mt][kt][1] = *(const uint32_t*)&As[(r + g + 8) * GP + kt * 16 + 2 * tig];
                a[mt][kt][2] = *(const uint32_t*)&As[(r + g)     * GP + kt * 16 + 2 * tig + 8];
                a[mt][kt][3] = *(const uint32_t*)&As[(r + g + 8) * GP + kt * 16 + 2 * tig + 8];
            }
        #pragma unroll
        for (int j = 0; j < 8; j++) {
            #pragma unroll
            for (int kt = 0; kt < 2; kt++) {
                uint32_t b[2];
                b[0] = *(const uint32_t*)&Bs[(8 * j + g) * GP + kt * 16 + 2 * tig];
                b[1] = *(const uint32_t*)&Bs[(8 * j + g) * GP + kt * 16 + 2 * tig + 8];
                mma16816(c[0][j], a[0][kt], b);
                mma16816(c[1][j], a[1][kt], b);
            }
        }
        __syncthreads();
    }

    #pragma unroll
    for (int mt = 0; mt < 2; mt++) {
        int r0 = m0 + w * 32 + mt * 16 + g;
        #pragma unroll
        for (int half = 0; half < 2; half++) {
            int m = r0 + half * 8;
            #pragma unroll
            for (int j = 0; j < 8; j++) {
                int n = n0 + 8 * j + 2 * tig;
                float2 xr = *(const float2*)(X + m * HH + n);
                float2 ov;
                ov.x = c[mt][j][half * 2 + 0] + bo[n]     + xr.x;
                ov.y = c[mt][j][half * 2 + 1] + bo[n + 1] + xr.y;
                *(float2*)&g_resid[m * HH + n] = ov;
            }
        }
    }
}

// ---------------------------------------------------------------------------
// Kernel 4: LayerNorm (unchanged)
// ---------------------------------------------------------------------------
__global__ __launch_bounds__(256) void ln_kernel(
    const float* __restrict__ gamma, const float* __restrict__ beta,
    float* __restrict__ out)
{
    const int lane = threadIdx.x & 31;
    const int warp = threadIdx.x >> 5;
    const int row  = blockIdx.x * 8 + warp;

    const float* r = g_resid + row * HH + lane * 8;
    float4 a  = *(const float4*)(r);
    float4 b4 = *(const float4*)(r + 4);

    float sum = a.x + a.y + a.z + a.w + b4.x + b4.y + b4.z + b4.w;
    #pragma unroll
    for (int off = 16; off; off >>= 1)
        sum += __shfl_xor_sync(0xffffffffu, sum, off);
    float mu = sum * (1.0f / 256.0f);

    float d0 = a.x - mu, d1 = a.y - mu, d2 = a.z - mu, d3 = a.w - mu;
    float d4 = b4.x - mu, d5 = b4.y - mu, d6 = b4.z - mu, d7 = b4.w - mu;
    float vs = d0 * d0 + d1 * d1 + d2 * d2 + d3 * d3
             + d4 * d4 + d5 * d5 + d6 * d6 + d7 * d7;
    #pragma unroll
    for (int off = 16; off; off >>= 1)
        vs += __shfl_xor_sync(0xffffffffu, vs, off);
    float inv = rsqrtf(vs * (1.0f / 256.0f) + 1e-12f);

    float4 g0 = *(const float4*)(gamma + lane * 8);
    float4 g1 = *(const float4*)(gamma + lane * 8 + 4);
    float4 e0 = *(const float4*)(beta + lane * 8);
    float4 e1 = *(const float4*)(beta + lane * 8 + 4);

    float4 o0, o1;
    o0.x = d0 * inv * g0.x + e0.x;
    o0.y = d1 * inv * g0.y + e0.y;
    o0.z = d2 * inv * g0.z + e0.z;
    o0.w = d3 * inv * g0.w + e0.w;
    o1.x = d4 * inv * g1.x + e1.x;
    o1.y = d5 * inv * g1.y + e1.y;
    o1.z = d6 * inv * g1.z + e1.z;
    o1.w = d7 * inv * g1.w + e1.w;

    float* op = out + row * HH + lane * 8;
    *(float4*)(op)     = o0;
    *(float4*)(op + 4) = o1;
}

// ---------------------------------------------------------------------------
extern "C" void kernel_launch(void* const* d_in, const int* in_sizes, int n_in,
                              void* d_out, int out_size)
{
    const float* X     = (const float*)d_in[0];
    const float* mask  = (const float*)d_in[1];
    const float* Wq    = (const float*)d_in[2];
    const float* bq    = (const float*)d_in[3];
    const float* Wk    = (const float*)d_in[4];
    const float* bk    = (const float*)d_in[5];
    const float* Wv    = (const float*)d_in[6];
    const float* bv    = (const float*)d_in[7];
    const float* Wo    = (const float*)d_in[8];
    const float* bo    = (const float*)d_in[9];
    const float* gamma = (const float*)d_in[10];
    const float* beta  = (const float*)d_in[11];
    float* out = (float*)d_out;

    cudaFuncSetAttribute(attn_kernel,
                         cudaFuncAttributeMaxDynamicSharedMemorySize, ATTN_SMEM);

    qkv_kernel<<<dim3(HH / 64, MTOT / 128, 3), 128>>>(X, Wq, bq, Wk, bk, Wv, bv);
    attn_kernel<<<dim3(BB * NHH, SS / 128), 256, ATTN_SMEM>>>(mask);
    proj_kernel<<<dim3(HH / 64, MTOT / 128), 128>>>(X, Wo, bo);
    ln_kernel<<<MTOT / 8, 256>>>(gamma, beta, out);
}

// round 10
// speedup vs baseline: 1.1108x; 1.1108x over previous
#include <cuda_runtime.h>
#include <cuda_bf16.h>
#include <stdint.h>
#include <math.h>

#define BB   8
#define SS   2048
#define HH   256
#define NHH  4
#define HDD  64
#define MTOT (BB * SS)   // 16384

// ---------------------------------------------------------------------------
// Scratch (__device__ globals only).
// ---------------------------------------------------------------------------
__device__ __align__(128) __nv_bfloat16 g_Qb[32 * SS * HDD];   // [bh][s][d]
__device__ __align__(128) __nv_bfloat16 g_Kb[32 * SS * HDD];   // [bh][s][d]
__device__ __align__(128) __nv_bfloat16 g_Vt[32 * HDD * SS];   // [bh][d][s] (transposed)
__device__ __align__(128) __nv_bfloat16 g_ctxb[MTOT * HH];     // [m][h*64+d]

// ---------------------------------------------------------------------------
// Helpers
// ---------------------------------------------------------------------------
__device__ __forceinline__ uint32_t packbf(float lo, float hi) {
    uint32_t r;
    asm("cvt.rn.bf16x2.f32 %0, %1, %2;" : "=r"(r) : "f"(hi), "f"(lo));
    return r;
}

__device__ __forceinline__ void mma16816(float* c, const uint32_t* a, const uint32_t* b) {
    asm volatile(
        "mma.sync.aligned.m16n8k16.row.col.f32.bf16.bf16.f32 "
        "{%0,%1,%2,%3}, {%4,%5,%6,%7}, {%8,%9}, {%0,%1,%2,%3};\n"
        : "+f"(c[0]), "+f"(c[1]), "+f"(c[2]), "+f"(c[3])
        : "r"(a[0]), "r"(a[1]), "r"(a[2]), "r"(a[3]), "r"(b[0]), "r"(b[1]));
}

__device__ __forceinline__ uint32_t smem_u32(const void* p) {
    uint32_t a;
    asm("{ .reg .u64 t; cvta.to.shared.u64 t, %1; cvt.u32.u64 %0, t; }" : "=r"(a) : "l"(p));
    return a;
}

__device__ __forceinline__ void ldsm4(uint32_t& r0, uint32_t& r1, uint32_t& r2, uint32_t& r3,
                                      uint32_t addr) {
    asm volatile("ldmatrix.sync.aligned.m8n8.x4.shared.b16 {%0,%1,%2,%3}, [%4];"
                 : "=r"(r0), "=r"(r1), "=r"(r2), "=r"(r3) : "r"(addr));
}

__device__ __forceinline__ void cp16(uint32_t dst, const void* src) {
    asm volatile("cp.async.cg.shared.global [%0], [%1], 16;" :: "r"(dst), "l"(src));
}
#define CP_COMMIT() asm volatile("cp.async.commit_group;" ::: "memory")
#define CP_WAIT1()  asm volatile("cp.async.wait_group 1;" ::: "memory")
#define CP_WAIT0()  asm volatile("cp.async.wait_group 0;" ::: "memory")

#define GP 40   // smem pitch for mma.sync GEMM tiles

// ---------------------------------------------------------------------------
// Kernel 1: QKV projection (bf16 mma.sync).
// Q,K split-head row-major; V transposed [bh][d][s] via SMEM transpose
// (coalesced 16B stores instead of 2B scatter at 4KB stride).
// ---------------------------------------------------------------------------
__global__ __launch_bounds__(128) void qkv_kernel(
    const float* __restrict__ X,
    const float* __restrict__ Wq, const float* __restrict__ bq,
    const float* __restrict__ Wk, const float* __restrict__ bk,
    const float* __restrict__ Wv, const float* __restrict__ bv)
{
    __shared__ __nv_bfloat16 As[128 * GP];
    __shared__ __nv_bfloat16 Bs[64 * GP];
    __shared__ __nv_bfloat16 Ts[64 * 136];   // V transpose staging [d][s_local]

    const int z = blockIdx.z;
    const float* W;  const float* bias;
    if (z == 0)      { W = Wq; bias = bq; }
    else if (z == 1) { W = Wk; bias = bk; }
    else             { W = Wv; bias = bv; }

    const int t = threadIdx.x;
    const int w = t >> 5, lane = t & 31;
    const int g = lane >> 2, tig = lane & 3;
    const int m0 = blockIdx.y * 128, n0 = blockIdx.x * 64;

    float c[2][8][4];
    #pragma unroll
    for (int mt = 0; mt < 2; mt++)
        #pragma unroll
        for (int j = 0; j < 8; j++)
            #pragma unroll
            for (int i = 0; i < 4; i++) c[mt][j][i] = 0.0f;

    for (int k0 = 0; k0 < HH; k0 += 32) {
        #pragma unroll
        for (int i = 0; i < 8; i++) {
            int m = (t >> 3) + 16 * i;
            int k = 4 * (t & 7);
            float4 v = *(const float4*)(X + (m0 + m) * HH + k0 + k);
            uint2 p;
            p.x = packbf(v.x, v.y);
            p.y = packbf(v.z, v.w);
            *(uint2*)&As[m * GP + k] = p;
        }
        #pragma unroll
        for (int i = 0; i < 8; i++) {
            int idx = 2 * t + 256 * i;
            int k = idx >> 6, n = idx & 63;
            float2 v = *(const float2*)(W + (k0 + k) * HH + n0 + n);
            Bs[n * GP + k]       = __float2bfloat16(v.x);
            Bs[(n + 1) * GP + k] = __float2bfloat16(v.y);
        }
        __syncthreads();

        uint32_t a[2][2][4];
        #pragma unroll
        for (int mt = 0; mt < 2; mt++)
            #pragma unroll
            for (int kt = 0; kt < 2; kt++) {
                int r = w * 32 + mt * 16;
                a[mt][kt][0] = *(const uint32_t*)&As[(r + g)     * GP + kt * 16 + 2 * tig];
                a[mt][kt][1] = *(const uint32_t*)&As[(r + g + 8) * GP + kt * 16 + 2 * tig];
                a[mt][kt][2] = *(const uint32_t*)&As[(r + g)     * GP + kt * 16 + 2 * tig + 8];
                a[mt][kt][3] = *(const uint32_t*)&As[(r + g + 8) * GP + kt * 16 + 2 * tig + 8];
            }
        #pragma unroll
        for (int j = 0; j < 8; j++) {
            #pragma unroll
            for (int kt = 0; kt < 2; kt++) {
                uint32_t b[2];
                b[0] = *(const uint32_t*)&Bs[(8 * j + g) * GP + kt * 16 + 2 * tig];
                b[1] = *(const uint32_t*)&Bs[(8 * j + g) * GP + kt * 16 + 2 * tig + 8];
                mma16816(c[0][j], a[0][kt], b);
                mma16816(c[1][j], a[1][kt], b);
            }
        }
        __syncthreads();
    }

    const int head = blockIdx.x;
    if (z != 2) {
        __nv_bfloat16* out = (z == 0) ? g_Qb : g_Kb;
        #pragma unroll
        for (int mt = 0; mt < 2; mt++) {
            int r0 = m0 + w * 32 + mt * 16 + g;
            #pragma unroll
            for (int half = 0; half < 2; half++) {
                int m  = r0 + half * 8;
                int b_ = m >> 11;
                int s_ = m & (SS - 1);
                int bh = b_ * NHH + head;
                #pragma unroll
                for (int j = 0; j < 8; j++) {
                    int d = 8 * j + 2 * tig;
                    float v0 = c[mt][j][half * 2 + 0] + bias[n0 + d];
                    float v1 = c[mt][j][half * 2 + 1] + bias[n0 + d + 1];
                    *(uint32_t*)&out[(bh * SS + s_) * HDD + d] = packbf(v0, v1);
                }
            }
        }
    } else {
        // V: write into Ts[d][s_local], then coalesced copy to g_Vt
        #pragma unroll
        for (int mt = 0; mt < 2; mt++) {
            #pragma unroll
            for (int half = 0; half < 2; half++) {
                int sl = w * 32 + mt * 16 + g + half * 8;   // local row
                #pragma unroll
                for (int j = 0; j < 8; j++) {
                    int d = 8 * j + 2 * tig;
                    float v0 = c[mt][j][half * 2 + 0] + bias[n0 + d];
                    float v1 = c[mt][j][half * 2 + 1] + bias[n0 + d + 1];
                    Ts[d * 136 + sl]       = __float2bfloat16(v0);
                    Ts[(d + 1) * 136 + sl] = __float2bfloat16(v1);
                }
            }
        }
        __syncthreads();
        int d = t >> 1, half = t & 1;
        int b_ = m0 >> 11;
        int s0 = m0 & (SS - 1);
        int bh = b_ * NHH + head;
        const uint4* src = (const uint4*)&Ts[d * 136 + half * 64];
        uint4* dst = (uint4*)&g_Vt[((size_t)bh * HDD + d) * SS + s0 + half * 64];
        #pragma unroll
        for (int i = 0; i < 8; i++) dst[i] = src[i];
    }
}

// ---------------------------------------------------------------------------
// Kernel 2: flash attention (R7 verbatim — best known config).
// BQ=128 (32 rows/warp), 128 threads, 2-buffer K/V/mask cp.async pipeline.
// Dynamic smem (102400 B): K0@0 K1@8192 V0@16384 V1@24576 (64x128B swizzled),
// M0@32768 M1@67584 (128 rows x 68 floats).
// ---------------------------------------------------------------------------
#define NIT 32            // SS / 64
#define SM_K0   0
#define SM_K1   8192
#define SM_V0   16384
#define SM_V1   24576
#define SM_M0   32768
#define SM_M1   67584
#define MPITCH  68        // floats per mask row (272 B, 16B-aligned)
#define ATTN_SMEM 102400

__global__ __launch_bounds__(128) void attn_kernel(const float* __restrict__ mask)
{
    extern __shared__ char dynsm[];

    const int t = threadIdx.x;
    const int w = t >> 5, lane = t & 31;
    const int g = lane >> 2, tig = lane & 3;
    const int bh = blockIdx.x;
    const int qb = blockIdx.y;
    const int b_ = bh >> 2;
    const int h_ = bh & 3;

    const uint32_t smb = smem_u32(dynsm);
    const uint32_t kbase[2] = { smb + SM_K0, smb + SM_K1 };
    const uint32_t vbase[2] = { smb + SM_V0, smb + SM_V1 };
    const uint32_t mbase[2] = { smb + SM_M0, smb + SM_M1 };
    float* const msm[2] = { (float*)(dynsm + SM_M0), (float*)(dynsm + SM_M1) };

    const __nv_bfloat16* Qg = g_Qb + (size_t)bh * SS * HDD;
    const char* Kg = (const char*)(g_Kb + (size_t)bh * SS * HDD);
    const char* Vg = (const char*)(g_Vt + (size_t)bh * HDD * SS);
    const float* Mb = mask + (size_t)b_ * SS * SS + (size_t)(qb * 128) * SS;

    // K/V cp.async chunk addressing
    int ld_src[4], ld_dst[4], ld_row[4];
    #pragma unroll
    for (int jc = 0; jc < 4; jc++) {
        int c = t + 128 * jc;
        int row = c >> 3, seg = c & 7;
        ld_row[jc] = row;
        ld_src[jc] = row * 128 + seg * 16;
        ld_dst[jc] = row * 128 + ((seg * 16) ^ ((row & 7) * 16));
    }
    // Mask chunk addressing
    int md_dst[16], md_row[16];
    #pragma unroll
    for (int jm = 0; jm < 16; jm++) {
        int c = t + 128 * jm;
        int row = c >> 4, seg = c & 15;
        md_row[jm] = row;
        md_dst[jm] = row * (MPITCH * 4) + seg * 16;
    }

    // ldmatrix addressing (B-frags for both S and PV loops)
    const int lrow = (lane & 7) | ((lane & 16) >> 1);
    const int lkb  = (lane & 8) ? 16 : 0;
    const int lxor = (lrow & 7) * 16;
    const int lbase = lrow * 128;

    // Q A-fragments (2 m-tiles of 16 rows), resident all iterations
    const int qrow[2] = { qb * 128 + w * 32 + g, qb * 128 + w * 32 + 16 + g };
    uint32_t aq[2][4][4];
    #pragma unroll
    for (int mt = 0; mt < 2; mt++) {
        const __nv_bfloat16* r0 = Qg + (size_t)qrow[mt] * HDD;
        const __nv_bfloat16* r1 = r0 + 8 * HDD;
        #pragma unroll
        for (int kt = 0; kt < 4; kt++) {
            aq[mt][kt][0] = *(const uint32_t*)(r0 + kt * 16 + 2 * tig);
            aq[mt][kt][1] = *(const uint32_t*)(r1 + kt * 16 + 2 * tig);
            aq[mt][kt][2] = *(const uint32_t*)(r0 + kt * 16 + 2 * tig + 8);
            aq[mt][kt][3] = *(const uint32_t*)(r1 + kt * 16 + 2 * tig + 8);
        }
    }

    auto load_tiles = [&](int it, int buf) {
        const char* Ks = Kg + (size_t)it * 64 * 128;
        #pragma unroll
        for (int jc = 0; jc < 4; jc++) {
            cp16(kbase[buf] + ld_dst[jc], Ks + ld_src[jc]);
            cp16(vbase[buf] + ld_dst[jc],
                 Vg + (size_t)ld_row[jc] * (SS * 2) + it * 128 + (t & 7) * 16);
        }
        #pragma unroll
        for (int jm = 0; jm < 16; jm++) {
            cp16(mbase[buf] + md_dst[jm],
                 (const char*)(Mb + (size_t)md_row[jm] * SS + it * 64) + (t & 15) * 16);
        }
        CP_COMMIT();
    };

    load_tiles(0, 0);
    load_tiles(1, 1);

    float o[2][8][4];
    #pragma unroll
    for (int mt = 0; mt < 2; mt++)
        #pragma unroll
        for (int j = 0; j < 8; j++)
            #pragma unroll
            for (int i = 0; i < 4; i++) o[mt][j][i] = 0.0f;
    float lacc[2][2] = {{0.0f, 0.0f}, {0.0f, 0.0f}};

    for (int i = 0; i < NIT; i++) {
        const int buf = i & 1;
        if (i < NIT - 1) { CP_WAIT1(); } else { CP_WAIT0(); }
        __syncthreads();

        // ---- S = Q @ K^T ----
        float c[2][8][4];
        #pragma unroll
        for (int mt = 0; mt < 2; mt++)
            #pragma unroll
            for (int j = 0; j < 8; j++)
                #pragma unroll
                for (int q = 0; q < 4; q++) c[mt][j][q] = 0.0f;

        #pragma unroll
        for (int jj = 0; jj < 4; jj++) {
            #pragma unroll
            for (int kt = 0; kt < 4; kt++) {
                uint32_t r0, r1, r2, r3;
                ldsm4(r0, r1, r2, r3,
                      kbase[buf] + jj * 2048 + lbase + ((kt * 32 + lkb) ^ lxor));
                uint32_t blo[2] = { r0, r1 }, bhi[2] = { r2, r3 };
                mma16816(c[0][2 * jj],     aq[0][kt], blo);
                mma16816(c[0][2 * jj + 1], aq[0][kt], bhi);
                mma16816(c[1][2 * jj],     aq[1][kt], blo);
                mma16816(c[1][2 * jj + 1], aq[1][kt], bhi);
            }
        }

        // ---- softmax (no max): p = exp(s/8 + mask), mask from SMEM ----
        uint32_t pa[2][4][4];
        #pragma unroll
        for (int mt = 0; mt < 2; mt++) {
            const float* mp0 = msm[buf] + (w * 32 + mt * 16 + g) * MPITCH + 2 * tig;
            const float* mp1 = mp0 + 8 * MPITCH;
            #pragma unroll
            for (int j = 0; j < 8; j++) {
                float2 mk0 = *(const float2*)(mp0 + 8 * j);
                float2 mk1 = *(const float2*)(mp1 + 8 * j);
                float p0 = __expf(fmaf(c[mt][j][0], 0.125f, mk0.x));
                float p1 = __expf(fmaf(c[mt][j][1], 0.125f, mk0.y));
                float p2 = __expf(fmaf(c[mt][j][2], 0.125f, mk1.x));
                float p3 = __expf(fmaf(c[mt][j][3], 0.125f, mk1.y));
                lacc[mt][0] += p0 + p1;
                lacc[mt][1] += p2 + p3;
                int kt = j >> 1, hi = (j & 1) * 2;
                pa[mt][kt][hi + 0] = packbf(p0, p1);
                pa[mt][kt][hi + 1] = packbf(p2, p3);
            }
        }

        // ---- O += P @ V (V tile is [d][kv], non-trans ldmatrix) ----
        #pragma unroll
        for (int jj = 0; jj < 4; jj++) {
            #pragma unroll
            for (int kt = 0; kt < 4; kt++) {
                uint32_t r0, r1, r2, r3;
                ldsm4(r0, r1, r2, r3,
                      vbase[buf] + jj * 2048 + lbase + ((kt * 32 + lkb) ^ lxor));
                uint32_t blo[2] = { r0, r1 }, bhi[2] = { r2, r3 };
                mma16816(o[0][2 * jj],     pa[0][kt], blo);
                mma16816(o[0][2 * jj + 1], pa[0][kt], bhi);
                mma16816(o[1][2 * jj],     pa[1][kt], blo);
                mma16816(o[1][2 * jj + 1], pa[1][kt], bhi);
            }
        }

        __syncthreads();

        if (i + 2 < NIT) load_tiles(i + 2, buf);
    }

    #pragma unroll
    for (int mt = 0; mt < 2; mt++)
        #pragma unroll
        for (int h = 0; h < 2; h++) {
            float v = lacc[mt][h];
            v += __shfl_xor_sync(0xffffffffu, v, 1);
            v += __shfl_xor_sync(0xffffffffu, v, 2);
            lacc[mt][h] = 1.0f / v;
        }

    #pragma unroll
    for (int mt = 0; mt < 2; mt++) {
        __nv_bfloat16* c0 = g_ctxb + ((size_t)b_ * SS + qrow[mt]) * HH + h_ * HDD;
        __nv_bfloat16* c1 = c0 + 8 * HH;
        #pragma unroll
        for (int j = 0; j < 8; j++) {
            int d = 8 * j + 2 * tig;
            *(uint32_t*)(c0 + d) = packbf(o[mt][j][0] * lacc[mt][0],
                                          o[mt][j][1] * lacc[mt][0]);
            *(uint32_t*)(c1 + d) = packbf(o[mt][j][2] * lacc[mt][1],
                                          o[mt][j][3] * lacc[mt][1]);
        }
    }
}

// ---------------------------------------------------------------------------
// Kernel 3: out projection + residual + LayerNorm fused.
// BM=64, BN=256 (full row per block), 128 threads / 4 warps (16 rows each).
// Epilogue: resid = ctx@Wo + bo + X, then exact two-pass LN, write d_out.
// ---------------------------------------------------------------------------
__global__ __launch_bounds__(128) void projln_kernel(
    const float* __restrict__ X,
    const float* __restrict__ Wo, const float* __restrict__ bo,
    const float* __restrict__ gamma, const float* __restrict__ beta,
    float* __restrict__ out)
{
    __shared__ __nv_bfloat16 As[64 * GP];     // ctx tile 64x32
    __shared__ __nv_bfloat16 Bs[256 * GP];    // Wo tile [n][k] 256x32
    __shared__ float sgb[256 * 3];            // gamma | beta | bo

    const int t = threadIdx.x;
    const int w = t >> 5, lane = t & 31;
    const int g = lane >> 2, tig = lane & 3;
    const int m0 = blockIdx.x * 64;

    // stage gamma/beta/bo once
    sgb[t]             = gamma[t];
    sgb[t + 128]       = gamma[t + 128];
    sgb[256 + t]       = beta[t];
    sgb[256 + t + 128] = beta[t + 128];
    sgb[512 + t]       = bo[t];
    sgb[512 + t + 128] = bo[t + 128];

    float c[32][4];
    #pragma unroll
    for (int j = 0; j < 32; j++)
        #pragma unroll
        for (int i = 0; i < 4; i++) c[j][i] = 0.0f;

    for (int k0 = 0; k0 < HH; k0 += 32) {
        // As: 64 rows x 32 k bf16 (direct copy from ctx)
        #pragma unroll
        for (int i = 0; i < 2; i++) {
            int chunk = t + 128 * i;          // 256 chunks of 8 elements
            int row = chunk >> 2, ks = (chunk & 3) * 8;
            *(uint4*)&As[row * GP + ks] =
                *(const uint4*)&g_ctxb[(m0 + row) * HH + k0 + ks];
        }
        // Bs: Wo 32 k x 256 n fp32 -> bf16 transposed [n][k]
        #pragma unroll
        for (int i = 0; i < 32; i++) {
            int idx = 2 * t + 256 * i;
            int k = idx >> 8, n = idx & 255;
            float2 v = *(const float2*)(Wo + (k0 + k) * HH + n);
            Bs[n * GP + k]       = __float2bfloat16(v.x);
            Bs[(n + 1) * GP + k] = __float2bfloat16(v.y);
        }
        __syncthreads();

        uint32_t a[2][4];
        int r = w * 16;
        #pragma unroll
        for (int kt = 0; kt < 2; kt++) {
            a[kt][0] = *(const uint32_t*)&As[(r + g)     * GP + kt * 16 + 2 * tig];
            a[kt][1] = *(const uint32_t*)&As[(r + g + 8) * GP + kt * 16 + 2 * tig];
            a[kt][2] = *(const uint32_t*)&As[(r + g)     * GP + kt * 16 + 2 * tig + 8];
            a[kt][3] = *(const uint32_t*)&As[(r + g + 8) * GP + kt * 16 + 2 * tig + 8];
        }
        #pragma unroll
        for (int j = 0; j < 32; j++) {
            #pragma unroll
            for (int kt = 0; kt < 2; kt++) {
                uint32_t b[2];
                b[0] = *(const uint32_t*)&Bs[(8 * j + g) * GP + kt * 16 + 2 * tig];
                b[1] = *(const uint32_t*)&Bs[(8 * j + g) * GP + kt * 16 + 2 * tig + 8];
                mma16816(c[j], a[kt], b);
            }
        }
        __syncthreads();
    }

    // ---- epilogue: + bo + X, then LN over each full row ----
    const int r0g = m0 + w * 16 + g;     // rows r0g (c[j][0..1]) and r0g+8 (c[j][2..3])
    float sum0 = 0.0f, sum1 = 0.0f;
    #pragma unroll
    for (int j = 0; j < 32; j++) {
        int n = 8 * j + 2 * tig;
        float2 x0 = *(const float2*)(X + (size_t)r0g * HH + n);
        float2 x1 = *(const float2*)(X + (size_t)(r0g + 8) * HH + n);
        float b0 = sgb[512 + n], b1 = sgb[512 + n + 1];
        c[j][0] += b0 + x0.x;
        c[j][1] += b1 + x0.y;
        c[j][2] += b0 + x1.x;
        c[j][3] += b1 + x1.y;
        sum0 += c[j][0] + c[j][1];
        sum1 += c[j][2] + c[j][3];
    }
    sum0 += __shfl_xor_sync(0xffffffffu, sum0, 1);
    sum0 += __shfl_xor_sync(0xffffffffu, sum0, 2);
    sum1 += __shfl_xor_sync(0xffffffffu, sum1, 1);
    sum1 += __shfl_xor_sync(0xffffffffu, sum1, 2);
    float mu0 = sum0 * (1.0f / 256.0f);
    float mu1 = sum1 * (1.0f / 256.0f);

    float vs0 = 0.0f, vs1 = 0.0f;
    #pragma unroll
    for (int j = 0; j < 32; j++) {
        float d0 = c[j][0] - mu0, d1 = c[j][1] - mu0;
        float d2 = c[j][2] - mu1, d3 = c[j][3] - mu1;
        vs0 += d0 * d0 + d1 * d1;
        vs1 += d2 * d2 + d3 * d3;
    }
    vs0 += __shfl_xor_sync(0xffffffffu, vs0, 1);
    vs0 += __shfl_xor_sync(0xffffffffu, vs0, 2);
    vs1 += __shfl_xor_sync(0xffffffffu, vs1, 1);
    vs1 += __shfl_xor_sync(0xffffffffu, vs1, 2);
    float inv0 = rsqrtf(vs0 * (1.0f / 256.0f) + 1e-12f);
    float inv1 = rsqrtf(vs1 * (1.0f / 256.0f) + 1e-12f);

    #pragma unroll
    for (int j = 0; j < 32; j++) {
        int n = 8 * j + 2 * tig;
        float ga0 = sgb[n], ga1 = sgb[n + 1];
        float be0 = sgb[256 + n], be1 = sgb[256 + n + 1];
        float2 o0, o1;
        o0.x = (c[j][0] - mu0) * inv0 * ga0 + be0;
        o0.y = (c[j][1] - mu0) * inv0 * ga1 + be1;
        o1.x = (c[j][2] - mu1) * inv1 * ga0 + be0;
        o1.y = (c[j][3] - mu1) * inv1 * ga1 + be1;
        *(float2*)(out + (size_t)r0g * HH + n)       = o0;
        *(float2*)(out + (size_t)(r0g + 8) * HH + n) = o1;
    }
}

// ---------------------------------------------------------------------------
extern "C" void kernel_launch(void* const* d_in, const int* in_sizes, int n_in,
                              void* d_out, int out_size)
{
    const float* X     = (const float*)d_in[0];
    const float* mask  = (const float*)d_in[1];
    const float* Wq    = (const float*)d_in[2];
    const float* bq    = (const float*)d_in[3];
    const float* Wk    = (const float*)d_in[4];
    const float* bk    = (const float*)d_in[5];
    const float* Wv    = (const float*)d_in[6];
    const float* bv    = (const float*)d_in[7];
    const float* Wo    = (const float*)d_in[8];
    const float* bo    = (const float*)d_in[9];
    const float* gamma = (const float*)d_in[10];
    const float* beta  = (const float*)d_in[11];
    float* out = (float*)d_out;

    cudaFuncSetAttribute(attn_kernel,
                         cudaFuncAttributeMaxDynamicSharedMemorySize, ATTN_SMEM);

    qkv_kernel<<<dim3(HH / 64, MTOT / 128, 3), 128>>>(X, Wq, bq, Wk, bk, Wv, bv);
    attn_kernel<<<dim3(BB * NHH, SS / 128), 128, ATTN_SMEM>>>(mask);
    projln_kernel<<<MTOT / 64, 128>>>(X, Wo, bo, gamma, beta, out);
}

// round 11
// speedup vs baseline: 1.1169x; 1.0055x over previous
#include <cuda_runtime.h>
#include <cuda_bf16.h>
#include <stdint.h>
#include <math.h>

#define BB   8
#define SS   2048
#define HH   256
#define NHH  4
#define HDD  64
#define MTOT (BB * SS)   // 16384

// ---------------------------------------------------------------------------
// Scratch (__device__ globals only).
// ---------------------------------------------------------------------------
__device__ __align__(128) __nv_bfloat16 g_Qb[32 * SS * HDD];   // [bh][s][d]
__device__ __align__(128) __nv_bfloat16 g_Kb[32 * SS * HDD];   // [bh][s][d]
__device__ __align__(128) __nv_bfloat16 g_Vt[32 * HDD * SS];   // [bh][d][s] (transposed)
__device__ __align__(128) __nv_bfloat16 g_ctxb[MTOT * HH];     // [m][h*64+d]

// ---------------------------------------------------------------------------
// Helpers
// ---------------------------------------------------------------------------
__device__ __forceinline__ uint32_t packbf(float lo, float hi) {
    uint32_t r;
    asm("cvt.rn.bf16x2.f32 %0, %1, %2;" : "=r"(r) : "f"(hi), "f"(lo));
    return r;
}

__device__ __forceinline__ void mma16816(float* c, const uint32_t* a, const uint32_t* b) {
    asm volatile(
        "mma.sync.aligned.m16n8k16.row.col.f32.bf16.bf16.f32 "
        "{%0,%1,%2,%3}, {%4,%5,%6,%7}, {%8,%9}, {%0,%1,%2,%3};\n"
        : "+f"(c[0]), "+f"(c[1]), "+f"(c[2]), "+f"(c[3])
        : "r"(a[0]), "r"(a[1]), "r"(a[2]), "r"(a[3]), "r"(b[0]), "r"(b[1]));
}

__device__ __forceinline__ uint32_t smem_u32(const void* p) {
    uint32_t a;
    asm("{ .reg .u64 t; cvta.to.shared.u64 t, %1; cvt.u32.u64 %0, t; }" : "=r"(a) : "l"(p));
    return a;
}

__device__ __forceinline__ void ldsm4(uint32_t& r0, uint32_t& r1, uint32_t& r2, uint32_t& r3,
                                      uint32_t addr) {
    asm volatile("ldmatrix.sync.aligned.m8n8.x4.shared.b16 {%0,%1,%2,%3}, [%4];"
                 : "=r"(r0), "=r"(r1), "=r"(r2), "=r"(r3) : "r"(addr));
}

__device__ __forceinline__ void cp16(uint32_t dst, const void* src) {
    asm volatile("cp.async.cg.shared.global [%0], [%1], 16;" :: "r"(dst), "l"(src));
}
#define CP_COMMIT() asm volatile("cp.async.commit_group;" ::: "memory")
#define CP_WAIT1()  asm volatile("cp.async.wait_group 1;" ::: "memory")
#define CP_WAIT0()  asm volatile("cp.async.wait_group 0;" ::: "memory")

#define GP  40   // smem pitch (bf16) for mma.sync GEMM tiles
#define GPB 80   // pitch in bytes

// ---------------------------------------------------------------------------
// Kernel 1: QKV projection (bf16 mma.sync) — fragment loads via ldmatrix.x4.
// Q,K split-head row-major; V transposed [bh][d][s] via SMEM transpose.
// ---------------------------------------------------------------------------
__global__ __launch_bounds__(128) void qkv_kernel(
    const float* __restrict__ X,
    const float* __restrict__ Wq, const float* __restrict__ bq,
    const float* __restrict__ Wk, const float* __restrict__ bk,
    const float* __restrict__ Wv, const float* __restrict__ bv)
{
    __shared__ __nv_bfloat16 As[128 * GP];
    __shared__ __nv_bfloat16 Bs[64 * GP];
    __shared__ __nv_bfloat16 Ts[64 * 136];   // V transpose staging [d][s_local]

    const int z = blockIdx.z;
    const float* W;  const float* bias;
    if (z == 0)      { W = Wq; bias = bq; }
    else if (z == 1) { W = Wk; bias = bk; }
    else             { W = Wv; bias = bv; }

    const int t = threadIdx.x;
    const int w = t >> 5, lane = t & 31;
    const int g = lane >> 2, tig = lane & 3;
    const int m0 = blockIdx.y * 128, n0 = blockIdx.x * 64;

    const uint32_t as_base = smem_u32(As);
    const uint32_t bs_base = smem_u32(Bs);

    // ldmatrix lane maps
    // A-frags (a0,a1,a2,a3) = (r0-7,k0-15B),(r8-15,k0-15B),(r0-7,k16-31B),(r8-15,k16-31B)
    const int arow_byte = ((lane & 7) + ((lane & 8) ? 8 : 0)) * GPB
                        + ((lane & 16) ? 16 : 0);
    // B-frags (attn pattern): rows (lane&7)|((lane&16)>>1), kbyte (lane&8)?16:0
    const int brow = (lane & 7) | ((lane & 16) >> 1);
    const int bkb  = (lane & 8) ? 16 : 0;

    float c[2][8][4];
    #pragma unroll
    for (int mt = 0; mt < 2; mt++)
        #pragma unroll
        for (int j = 0; j < 8; j++)
            #pragma unroll
            for (int i = 0; i < 4; i++) c[mt][j][i] = 0.0f;

    for (int k0 = 0; k0 < HH; k0 += 32) {
        #pragma unroll
        for (int i = 0; i < 8; i++) {
            int m = (t >> 3) + 16 * i;
            int k = 4 * (t & 7);
            float4 v = *(const float4*)(X + (m0 + m) * HH + k0 + k);
            uint2 p;
            p.x = packbf(v.x, v.y);
            p.y = packbf(v.z, v.w);
            *(uint2*)&As[m * GP + k] = p;
        }
        #pragma unroll
        for (int i = 0; i < 8; i++) {
            int idx = 2 * t + 256 * i;
            int k = idx >> 6, n = idx & 63;
            float2 v = *(const float2*)(W + (k0 + k) * HH + n0 + n);
            Bs[n * GP + k]       = __float2bfloat16(v.x);
            Bs[(n + 1) * GP + k] = __float2bfloat16(v.y);
        }
        __syncthreads();

        uint32_t a[2][2][4];
        #pragma unroll
        for (int mt = 0; mt < 2; mt++)
            #pragma unroll
            for (int kt = 0; kt < 2; kt++)
                ldsm4(a[mt][kt][0], a[mt][kt][1], a[mt][kt][2], a[mt][kt][3],
                      as_base + (w * 32 + mt * 16) * GPB + arow_byte + kt * 32);

        #pragma unroll
        for (int jp = 0; jp < 4; jp++) {          // 4 j-pairs cover 8 n-blocks
            #pragma unroll
            for (int kt = 0; kt < 2; kt++) {
                uint32_t r0, r1, r2, r3;
                ldsm4(r0, r1, r2, r3,
                      bs_base + (16 * jp + brow) * GPB + bkb + kt * 32);
                uint32_t blo[2] = { r0, r1 }, bhi[2] = { r2, r3 };
                mma16816(c[0][2 * jp],     a[0][kt], blo);
                mma16816(c[0][2 * jp + 1], a[0][kt], bhi);
                mma16816(c[1][2 * jp],     a[1][kt], blo);
                mma16816(c[1][2 * jp + 1], a[1][kt], bhi);
            }
        }
        __syncthreads();
    }

    const int head = blockIdx.x;
    if (z != 2) {
        __nv_bfloat16* out = (z == 0) ? g_Qb : g_Kb;
        #pragma unroll
        for (int mt = 0; mt < 2; mt++) {
            int r0 = m0 + w * 32 + mt * 16 + g;
            #pragma unroll
            for (int half = 0; half < 2; half++) {
                int m  = r0 + half * 8;
                int b_ = m >> 11;
                int s_ = m & (SS - 1);
                int bh = b_ * NHH + head;
                #pragma unroll
                for (int j = 0; j < 8; j++) {
                    int d = 8 * j + 2 * tig;
                    float v0 = c[mt][j][half * 2 + 0] + bias[n0 + d];
                    float v1 = c[mt][j][half * 2 + 1] + bias[n0 + d + 1];
                    *(uint32_t*)&out[(bh * SS + s_) * HDD + d] = packbf(v0, v1);
                }
            }
        }
    } else {
        // V: write into Ts[d][s_local], then coalesced copy to g_Vt
        #pragma unroll
        for (int mt = 0; mt < 2; mt++) {
            #pragma unroll
            for (int half = 0; half < 2; half++) {
                int sl = w * 32 + mt * 16 + g + half * 8;   // local row
                #pragma unroll
                for (int j = 0; j < 8; j++) {
                    int d = 8 * j + 2 * tig;
                    float v0 = c[mt][j][half * 2 + 0] + bias[n0 + d];
                    float v1 = c[mt][j][half * 2 + 1] + bias[n0 + d + 1];
                    Ts[d * 136 + sl]       = __float2bfloat16(v0);
                    Ts[(d + 1) * 136 + sl] = __float2bfloat16(v1);
                }
            }
        }
        __syncthreads();
        int d = t >> 1, half = t & 1;
        int b_ = m0 >> 11;
        int s0 = m0 & (SS - 1);
        int bh = b_ * NHH + head;
        const uint4* src = (const uint4*)&Ts[d * 136 + half * 64];
        uint4* dst = (uint4*)&g_Vt[((size_t)bh * HDD + d) * SS + s0 + half * 64];
        #pragma unroll
        for (int i = 0; i < 8; i++) dst[i] = src[i];
    }
}

// ---------------------------------------------------------------------------
// Kernel 2: flash attention (R7/R10 verbatim — best known config).
// BQ=128 (32 rows/warp), 128 threads, 2-buffer K/V/mask cp.async pipeline.
// ---------------------------------------------------------------------------
#define NIT 32            // SS / 64
#define SM_K0   0
#define SM_K1   8192
#define SM_V0   16384
#define SM_V1   24576
#define SM_M0   32768
#define SM_M1   67584
#define MPITCH  68        // floats per mask row (272 B, 16B-aligned)
#define ATTN_SMEM 102400

__global__ __launch_bounds__(128) void attn_kernel(const float* __restrict__ mask)
{
    extern __shared__ char dynsm[];

    const int t = threadIdx.x;
    const int w = t >> 5, lane = t & 31;
    const int g = lane >> 2, tig = lane & 3;
    const int bh = blockIdx.x;
    const int qb = blockIdx.y;
    const int b_ = bh >> 2;
    const int h_ = bh & 3;

    const uint32_t smb = smem_u32(dynsm);
    const uint32_t kbase[2] = { smb + SM_K0, smb + SM_K1 };
    const uint32_t vbase[2] = { smb + SM_V0, smb + SM_V1 };
    const uint32_t mbase[2] = { smb + SM_M0, smb + SM_M1 };
    float* const msm[2] = { (float*)(dynsm + SM_M0), (float*)(dynsm + SM_M1) };

    const __nv_bfloat16* Qg = g_Qb + (size_t)bh * SS * HDD;
    const char* Kg = (const char*)(g_Kb + (size_t)bh * SS * HDD);
    const char* Vg = (const char*)(g_Vt + (size_t)bh * HDD * SS);
    const float* Mb = mask + (size_t)b_ * SS * SS + (size_t)(qb * 128) * SS;

    // K/V cp.async chunk addressing
    int ld_src[4], ld_dst[4], ld_row[4];
    #pragma unroll
    for (int jc = 0; jc < 4; jc++) {
        int c = t + 128 * jc;
        int row = c >> 3, seg = c & 7;
        ld_row[jc] = row;
        ld_src[jc] = row * 128 + seg * 16;
        ld_dst[jc] = row * 128 + ((seg * 16) ^ ((row & 7) * 16));
    }
    // Mask chunk addressing
    int md_dst[16], md_row[16];
    #pragma unroll
    for (int jm = 0; jm < 16; jm++) {
        int c = t + 128 * jm;
        int row = c >> 4, seg = c & 15;
        md_row[jm] = row;
        md_dst[jm] = row * (MPITCH * 4) + seg * 16;
    }

    // ldmatrix addressing (B-frags for both S and PV loops)
    const int lrow = (lane & 7) | ((lane & 16) >> 1);
    const int lkb  = (lane & 8) ? 16 : 0;
    const int lxor = (lrow & 7) * 16;
    const int lbase = lrow * 128;

    // Q A-fragments (2 m-tiles of 16 rows), resident all iterations
    const int qrow[2] = { qb * 128 + w * 32 + g, qb * 128 + w * 32 + 16 + g };
    uint32_t aq[2][4][4];
    #pragma unroll
    for (int mt = 0; mt < 2; mt++) {
        const __nv_bfloat16* r0 = Qg + (size_t)qrow[mt] * HDD;
        const __nv_bfloat16* r1 = r0 + 8 * HDD;
        #pragma unroll
        for (int kt = 0; kt < 4; kt++) {
            aq[mt][kt][0] = *(const uint32_t*)(r0 + kt * 16 + 2 * tig);
            aq[mt][kt][1] = *(const uint32_t*)(r1 + kt * 16 + 2 * tig);
            aq[mt][kt][2] = *(const uint32_t*)(r0 + kt * 16 + 2 * tig + 8);
            aq[mt][kt][3] = *(const uint32_t*)(r1 + kt * 16 + 2 * tig + 8);
        }
    }

    auto load_tiles = [&](int it, int buf) {
        const char* Ks = Kg + (size_t)it * 64 * 128;
        #pragma unroll
        for (int jc = 0; jc < 4; jc++) {
            cp16(kbase[buf] + ld_dst[jc], Ks + ld_src[jc]);
            cp16(vbase[buf] + ld_dst[jc],
                 Vg + (size_t)ld_row[jc] * (SS * 2) + it * 128 + (t & 7) * 16);
        }
        #pragma unroll
        for (int jm = 0; jm < 16; jm++) {
            cp16(mbase[buf] + md_dst[jm],
                 (const char*)(Mb + (size_t)md_row[jm] * SS + it * 64) + (t & 15) * 16);
        }
        CP_COMMIT();
    };

    load_tiles(0, 0);
    load_tiles(1, 1);

    float o[2][8][4];
    #pragma unroll
    for (int mt = 0; mt < 2; mt++)
        #pragma unroll
        for (int j = 0; j < 8; j++)
            #pragma unroll
            for (int i = 0; i < 4; i++) o[mt][j][i] = 0.0f;
    float lacc[2][2] = {{0.0f, 0.0f}, {0.0f, 0.0f}};

    for (int i = 0; i < NIT; i++) {
        const int buf = i & 1;
        if (i < NIT - 1) { CP_WAIT1(); } else { CP_WAIT0(); }
        __syncthreads();

        // ---- S = Q @ K^T ----
        float c[2][8][4];
        #pragma unroll
        for (int mt = 0; mt < 2; mt++)
            #pragma unroll
            for (int j = 0; j < 8; j++)
                #pragma unroll
                for (int q = 0; q < 4; q++) c[mt][j][q] = 0.0f;

        #pragma unroll
        for (int jj = 0; jj < 4; jj++) {
            #pragma unroll
            for (int kt = 0; kt < 4; kt++) {
                uint32_t r0, r1, r2, r3;
                ldsm4(r0, r1, r2, r3,
                      kbase[buf] + jj * 2048 + lbase + ((kt * 32 + lkb) ^ lxor));
                uint32_t blo[2] = { r0, r1 }, bhi[2] = { r2, r3 };
                mma16816(c[0][2 * jj],     aq[0][kt], blo);
                mma16816(c[0][2 * jj + 1], aq[0][kt], bhi);
                mma16816(c[1][2 * jj],     aq[1][kt], blo);
                mma16816(c[1][2 * jj + 1], aq[1][kt], bhi);
            }
        }

        // ---- softmax (no max): p = exp(s/8 + mask), mask from SMEM ----
        uint32_t pa[2][4][4];
        #pragma unroll
        for (int mt = 0; mt < 2; mt++) {
            const float* mp0 = msm[buf] + (w * 32 + mt * 16 + g) * MPITCH + 2 * tig;
            const float* mp1 = mp0 + 8 * MPITCH;
            #pragma unroll
            for (int j = 0; j < 8; j++) {
                float2 mk0 = *(const float2*)(mp0 + 8 * j);
                float2 mk1 = *(const float2*)(mp1 + 8 * j);
                float p0 = __expf(fmaf(c[mt][j][0], 0.125f, mk0.x));
                float p1 = __expf(fmaf(c[mt][j][1], 0.125f, mk0.y));
                float p2 = __expf(fmaf(c[mt][j][2], 0.125f, mk1.x));
                float p3 = __expf(fmaf(c[mt][j][3], 0.125f, mk1.y));
                lacc[mt][0] += p0 + p1;
                lacc[mt][1] += p2 + p3;
                int kt = j >> 1, hi = (j & 1) * 2;
                pa[mt][kt][hi + 0] = packbf(p0, p1);
                pa[mt][kt][hi + 1] = packbf(p2, p3);
            }
        }

        // ---- O += P @ V (V tile is [d][kv], non-trans ldmatrix) ----
        #pragma unroll
        for (int jj = 0; jj < 4; jj++) {
            #pragma unroll
            for (int kt = 0; kt < 4; kt++) {
                uint32_t r0, r1, r2, r3;
                ldsm4(r0, r1, r2, r3,
                      vbase[buf] + jj * 2048 + lbase + ((kt * 32 + lkb) ^ lxor));
                uint32_t blo[2] = { r0, r1 }, bhi[2] = { r2, r3 };
                mma16816(o[0][2 * jj],     pa[0][kt], blo);
                mma16816(o[0][2 * jj + 1], pa[0][kt], bhi);
                mma16816(o[1][2 * jj],     pa[1][kt], blo);
                mma16816(o[1][2 * jj + 1], pa[1][kt], bhi);
            }
        }

        __syncthreads();

        if (i + 2 < NIT) load_tiles(i + 2, buf);
    }

    #pragma unroll
    for (int mt = 0; mt < 2; mt++)
        #pragma unroll
        for (int h = 0; h < 2; h++) {
            float v = lacc[mt][h];
            v += __shfl_xor_sync(0xffffffffu, v, 1);
            v += __shfl_xor_sync(0xffffffffu, v, 2);
            lacc[mt][h] = 1.0f / v;
        }

    #pragma unroll
    for (int mt = 0; mt < 2; mt++) {
        __nv_bfloat16* c0 = g_ctxb + ((size_t)b_ * SS + qrow[mt]) * HH + h_ * HDD;
        __nv_bfloat16* c1 = c0 + 8 * HH;
        #pragma unroll
        for (int j = 0; j < 8; j++) {
            int d = 8 * j + 2 * tig;
            *(uint32_t*)(c0 + d) = packbf(o[mt][j][0] * lacc[mt][0],
                                          o[mt][j][1] * lacc[mt][0]);
            *(uint32_t*)(c1 + d) = packbf(o[mt][j][2] * lacc[mt][1],
                                          o[mt][j][3] * lacc[mt][1]);
        }
    }
}

// ---------------------------------------------------------------------------
// Kernel 3: out projection + residual + LayerNorm fused (ldmatrix frags).
// BM=64, BN=256 (full row per block), 128 threads / 4 warps (16 rows each).
// ---------------------------------------------------------------------------
__global__ __launch_bounds__(128) void projln_kernel(
    const float* __restrict__ X,
    const float* __restrict__ Wo, const float* __restrict__ bo,
    const float* __restrict__ gamma, const float* __restrict__ beta,
    float* __restrict__ out)
{
    __shared__ __nv_bfloat16 As[64 * GP];     // ctx tile 64x32
    __shared__ __nv_bfloat16 Bs[256 * GP];    // Wo tile [n][k] 256x32
    __shared__ float sgb[256 * 3];            // gamma | beta | bo

    const int t = threadIdx.x;
    const int w = t >> 5, lane = t & 31;
    const int g = lane >> 2, tig = lane & 3;
    const int m0 = blockIdx.x * 64;

    const uint32_t as_base = smem_u32(As);
    const uint32_t bs_base = smem_u32(Bs);

    const int arow_byte = ((lane & 7) + ((lane & 8) ? 8 : 0)) * GPB
                        + ((lane & 16) ? 16 : 0);
    const int brow = (lane & 7) | ((lane & 16) >> 1);
    const int bkb  = (lane & 8) ? 16 : 0;

    // stage gamma/beta/bo once
    sgb[t]             = gamma[t];
    sgb[t + 128]       = gamma[t + 128];
    sgb[256 + t]       = beta[t];
    sgb[256 + t + 128] = beta[t + 128];
    sgb[512 + t]       = bo[t];
    sgb[512 + t + 128] = bo[t + 128];

    float c[32][4];
    #pragma unroll
    for (int j = 0; j < 32; j++)
        #pragma unroll
        for (int i = 0; i < 4; i++) c[j][i] = 0.0f;

    for (int k0 = 0; k0 < HH; k0 += 32) {
        // As: 64 rows x 32 k bf16 (direct copy from ctx)
        #pragma unroll
        for (int i = 0; i < 2; i++) {
            int chunk = t + 128 * i;          // 256 chunks of 8 elements
            int row = chunk >> 2, ks = (chunk & 3) * 8;
            *(uint4*)&As[row * GP + ks] =
                *(const uint4*)&g_ctxb[(m0 + row) * HH + k0 + ks];
        }
        // Bs: Wo 32 k x 256 n fp32 -> bf16 transposed [n][k]
        #pragma unroll
        for (int i = 0; i < 32; i++) {
            int idx = 2 * t + 256 * i;
            int k = idx >> 8, n = idx & 255;
            float2 v = *(const float2*)(Wo + (k0 + k) * HH + n);
            Bs[n * GP + k]       = __float2bfloat16(v.x);
            Bs[(n + 1) * GP + k] = __float2bfloat16(v.y);
        }
        __syncthreads();

        uint32_t a[2][4];
        #pragma unroll
        for (int kt = 0; kt < 2; kt++)
            ldsm4(a[kt][0], a[kt][1], a[kt][2], a[kt][3],
                  as_base + (w * 16) * GPB + arow_byte + kt * 32);

        #pragma unroll
        for (int jp = 0; jp < 16; jp++) {         // 16 j-pairs cover 32 n-blocks
            #pragma unroll
            for (int kt = 0; kt < 2; kt++) {
                uint32_t r0, r1, r2, r3;
                ldsm4(r0, r1, r2, r3,
                      bs_base + (16 * jp + brow) * GPB + bkb + kt * 32);
                uint32_t blo[2] = { r0, r1 }, bhi[2] = { r2, r3 };
                mma16816(c[2 * jp],     a[kt], blo);
                mma16816(c[2 * jp + 1], a[kt], bhi);
            }
        }
        __syncthreads();
    }

    // ---- epilogue: + bo + X, then LN over each full row ----
    const int r0g = m0 + w * 16 + g;     // rows r0g (c[j][0..1]) and r0g+8 (c[j][2..3])
    float sum0 = 0.0f, sum1 = 0.0f;
    #pragma unroll
    for (int j = 0; j < 32; j++) {
        int n = 8 * j + 2 * tig;
        float2 x0 = *(const float2*)(X + (size_t)r0g * HH + n);
        float2 x1 = *(const float2*)(X + (size_t)(r0g + 8) * HH + n);
        float b0 = sgb[512 + n], b1 = sgb[512 + n + 1];
        c[j][0] += b0 + x0.x;
        c[j][1] += b1 + x0.y;
        c[j][2] += b0 + x1.x;
        c[j][3] += b1 + x1.y;
        sum0 += c[j][0] + c[j][1];
        sum1 += c[j][2] + c[j][3];
    }
    sum0 += __shfl_xor_sync(0xffffffffu, sum0, 1);
    sum0 += __shfl_xor_sync(0xffffffffu, sum0, 2);
    sum1 += __shfl_xor_sync(0xffffffffu, sum1, 1);
    sum1 += __shfl_xor_sync(0xffffffffu, sum1, 2);
    float mu0 = sum0 * (1.0f / 256.0f);
    float mu1 = sum1 * (1.0f / 256.0f);

    float vs0 = 0.0f, vs1 = 0.0f;
    #pragma unroll
    for (int j = 0; j < 32; j++) {
        float d0 = c[j][0] - mu0, d1 = c[j][1] - mu0;
        float d2 = c[j][2] - mu1, d3 = c[j][3] - mu1;
        vs0 += d0 * d0 + d1 * d1;
        vs1 += d2 * d2 + d3 * d3;
    }
    vs0 += __shfl_xor_sync(0xffffffffu, vs0, 1);
    vs0 += __shfl_xor_sync(0xffffffffu, vs0, 2);
    vs1 += __shfl_xor_sync(0xffffffffu, vs1, 1);
    vs1 += __shfl_xor_sync(0xffffffffu, vs1, 2);
    float inv0 = rsqrtf(vs0 * (1.0f / 256.0f) + 1e-12f);
    float inv1 = rsqrtf(vs1 * (1.0f / 256.0f) + 1e-12f);

    #pragma unroll
    for (int j = 0; j < 32; j++) {
        int n = 8 * j + 2 * tig;
        float ga0 = sgb[n], ga1 = sgb[n + 1];
        float be0 = sgb[256 + n], be1 = sgb[256 + n + 1];
        float2 o0, o1;
        o0.x = (c[j][0] - mu0) * inv0 * ga0 + be0;
        o0.y = (c[j][1] - mu0) * inv0 * ga1 + be1;
        o1.x = (c[j][2] - mu1) * inv1 * ga0 + be0;
        o1.y = (c[j][3] - mu1) * inv1 * ga1 + be1;
        *(float2*)(out + (size_t)r0g * HH + n)       = o0;
        *(float2*)(out + (size_t)(r0g + 8) * HH + n) = o1;
    }
}

// ---------------------------------------------------------------------------
extern "C" void kernel_launch(void* const* d_in, const int* in_sizes, int n_in,
                              void* d_out, int out_size)
{
    const float* X     = (const float*)d_in[0];
    const float* mask  = (const float*)d_in[1];
    const float* Wq    = (const float*)d_in[2];
    const float* bq    = (const float*)d_in[3];
    const float* Wk    = (const float*)d_in[4];
    const float* bk    = (const float*)d_in[5];
    const float* Wv    = (const float*)d_in[6];
    const float* bv    = (const float*)d_in[7];
    const float* Wo    = (const float*)d_in[8];
    const float* bo    = (const float*)d_in[9];
    const float* gamma = (const float*)d_in[10];
    const float* beta  = (const float*)d_in[11];
    float* out = (float*)d_out;

    cudaFuncSetAttribute(attn_kernel,
                         cudaFuncAttributeMaxDynamicSharedMemorySize, ATTN_SMEM);

    qkv_kernel<<<dim3(HH / 64, MTOT / 128, 3), 128>>>(X, Wq, bq, Wk, bk, Wv, bv);
    attn_kernel<<<dim3(BB * NHH, SS / 128), 128, ATTN_SMEM>>>(mask);
    projln_kernel<<<MTOT / 64, 128>>>(X, Wo, bo, gamma, beta, out);
}

// round 12
// speedup vs baseline: 1.3679x; 1.2248x over previous
#include <cuda_runtime.h>
#include <cuda_bf16.h>
#include <stdint.h>
#include <math.h>

#define BB   8
#define SS   2048
#define HH   256
#define NHH  4
#define HDD  64
#define MTOT (BB * SS)   // 16384

// ---------------------------------------------------------------------------
// Scratch (__device__ globals only).
// ---------------------------------------------------------------------------
__device__ __align__(128) __nv_bfloat16 g_Xb[MTOT * HH];       // X in bf16
__device__ __align__(128) __nv_bfloat16 g_Wtq[HH * HH];        // W^T bf16 [n][k]
__device__ __align__(128) __nv_bfloat16 g_Wtk[HH * HH];
__device__ __align__(128) __nv_bfloat16 g_Wtv[HH * HH];
__device__ __align__(128) __nv_bfloat16 g_Wto[HH * HH];
__device__ __align__(128) __nv_bfloat16 g_Qb[32 * SS * HDD];   // [bh][s][d]
__device__ __align__(128) __nv_bfloat16 g_Kb[32 * SS * HDD];   // [bh][s][d]
__device__ __align__(128) __nv_bfloat16 g_Vt[32 * HDD * SS];   // [bh][d][s]
__device__ __align__(128) __nv_bfloat16 g_ctxb[MTOT * HH];     // [m][h*64+d]

// ---------------------------------------------------------------------------
// Helpers
// ---------------------------------------------------------------------------
__device__ __forceinline__ uint32_t packbf(float lo, float hi) {
    uint32_t r;
    asm("cvt.rn.bf16x2.f32 %0, %1, %2;" : "=r"(r) : "f"(hi), "f"(lo));
    return r;
}

__device__ __forceinline__ void mma16816(float* c, const uint32_t* a, const uint32_t* b) {
    asm volatile(
        "mma.sync.aligned.m16n8k16.row.col.f32.bf16.bf16.f32 "
        "{%0,%1,%2,%3}, {%4,%5,%6,%7}, {%8,%9}, {%0,%1,%2,%3};\n"
        : "+f"(c[0]), "+f"(c[1]), "+f"(c[2]), "+f"(c[3])
        : "r"(a[0]), "r"(a[1]), "r"(a[2]), "r"(a[3]), "r"(b[0]), "r"(b[1]));
}

__device__ __forceinline__ uint32_t smem_u32(const void* p) {
    uint32_t a;
    asm("{ .reg .u64 t; cvta.to.shared.u64 t, %1; cvt.u32.u64 %0, t; }" : "=r"(a) : "l"(p));
    return a;
}

__device__ __forceinline__ void ldsm4(uint32_t& r0, uint32_t& r1, uint32_t& r2, uint32_t& r3,
                                      uint32_t addr) {
    asm volatile("ldmatrix.sync.aligned.m8n8.x4.shared.b16 {%0,%1,%2,%3}, [%4];"
                 : "=r"(r0), "=r"(r1), "=r"(r2), "=r"(r3) : "r"(addr));
}

__device__ __forceinline__ void cp16(uint32_t dst, const void* src) {
    asm volatile("cp.async.cg.shared.global [%0], [%1], 16;" :: "r"(dst), "l"(src));
}
#define CP_COMMIT() asm volatile("cp.async.commit_group;" ::: "memory")
#define CP_WAIT1()  asm volatile("cp.async.wait_group 1;" ::: "memory")
#define CP_WAIT0()  asm volatile("cp.async.wait_group 0;" ::: "memory")

// ---------------------------------------------------------------------------
// Kernel 0a: X fp32 -> bf16
// ---------------------------------------------------------------------------
__global__ __launch_bounds__(256) void cvt_x_kernel(const float* __restrict__ X)
{
    int idx = (blockIdx.x * 256 + threadIdx.x) * 8;
    float4 v0 = *(const float4*)(X + idx);
    float4 v1 = *(const float4*)(X + idx + 4);
    uint4 o;
    o.x = packbf(v0.x, v0.y);
    o.y = packbf(v0.z, v0.w);
    o.z = packbf(v1.x, v1.y);
    o.w = packbf(v1.z, v1.w);
    *(uint4*)&g_Xb[idx] = o;
}

// ---------------------------------------------------------------------------
// Kernel 0b: W fp32 [k][n] -> bf16 transposed [n][k]  (32x32 smem transpose)
// ---------------------------------------------------------------------------
__global__ __launch_bounds__(256) void cvt_w_kernel(
    const float* __restrict__ Wq, const float* __restrict__ Wk,
    const float* __restrict__ Wv, const float* __restrict__ Wo)
{
    __shared__ float sm[32][33];
    const float* W;  __nv_bfloat16* out;
    if (blockIdx.z == 0)      { W = Wq; out = g_Wtq; }
    else if (blockIdx.z == 1) { W = Wk; out = g_Wtk; }
    else if (blockIdx.z == 2) { W = Wv; out = g_Wtv; }
    else                      { W = Wo; out = g_Wto; }

    const int k0 = blockIdx.x * 32, n0 = blockIdx.y * 32;
    const int x = threadIdx.x & 31, y = threadIdx.x >> 5;
    #pragma unroll
    for (int i = 0; i < 4; i++) {
        int r = y + 8 * i;
        sm[r][x] = W[(k0 + r) * HH + n0 + x];
    }
    __syncthreads();
    #pragma unroll
    for (int i = 0; i < 4; i++) {
        int nr = y + 8 * i;
        out[(n0 + nr) * HH + k0 + x] = __float2bfloat16(sm[x][nr]);
    }
}

// ---------------------------------------------------------------------------
// Kernel 1: QKV projection — all-bf16, cp.async double-buffered, ldmatrix.
// BM=128, BN=64, BK=64 (4 k-iters). Dynamic smem 49152 B:
//   A0@0, A1@16384 (128x128B swizzled), B0@32768, B1@40960 (64x128B swizzled)
// Epilogue: Q,K split-head row-major; V transposed via Ts (aliases A0/A1).
// ---------------------------------------------------------------------------
#define QSM_A0 0
#define QSM_A1 16384
#define QSM_B0 32768
#define QSM_B1 40960
#define QKV_SMEM 49152

__global__ __launch_bounds__(128) void qkv_kernel(
    const float* __restrict__ bq, const float* __restrict__ bk,
    const float* __restrict__ bv)
{
    extern __shared__ char qsm[];

    const int z = blockIdx.z;
    const __nv_bfloat16* Wt;  const float* bias;
    if (z == 0)      { Wt = g_Wtq; bias = bq; }
    else if (z == 1) { Wt = g_Wtk; bias = bk; }
    else             { Wt = g_Wtv; bias = bv; }

    const int t = threadIdx.x;
    const int w = t >> 5, lane = t & 31;
    const int g = lane >> 2, tig = lane & 3;
    const int m0 = blockIdx.y * 128, n0 = blockIdx.x * 64;

    const uint32_t smb = smem_u32(qsm);
    const uint32_t abase[2] = { smb + QSM_A0, smb + QSM_A1 };
    const uint32_t bbase[2] = { smb + QSM_B0, smb + QSM_B1 };

    const char* Xa = (const char*)g_Xb + (size_t)m0 * 512;   // 512 B per row
    const char* Wa = (const char*)Wt  + (size_t)n0 * 512;

    // frag lane maps (proven): A from R11, B from attn
    const int ar   = (lane & 7) + ((lane & 8) ? 8 : 0);
    const int ak   = (lane & 16) ? 16 : 0;
    const int axor = (lane & 7) * 16;
    const int brow = (lane & 7) | ((lane & 16) >> 1);
    const int bkb  = (lane & 8) ? 16 : 0;
    const int bxor = (brow & 7) * 16;

    auto load_tiles = [&](int ki, int buf) {
        const int kb = ki * 128;   // byte offset of this k-chunk within a row
        #pragma unroll
        for (int j = 0; j < 8; j++) {            // A: 1024 chunks
            int c = t + 128 * j;
            int row = c >> 3, seg = c & 7;
            cp16(abase[buf] + row * 128 + ((seg * 16) ^ ((row & 7) * 16)),
                 Xa + (size_t)row * 512 + kb + seg * 16);
        }
        #pragma unroll
        for (int j = 0; j < 4; j++) {            // B: 512 chunks
            int c = t + 128 * j;
            int row = c >> 3, seg = c & 7;
            cp16(bbase[buf] + row * 128 + ((seg * 16) ^ ((row & 7) * 16)),
                 Wa + (size_t)row * 512 + kb + seg * 16);
        }
        CP_COMMIT();
    };

    load_tiles(0, 0);
    load_tiles(1, 1);

    float c[2][8][4];
    #pragma unroll
    for (int mt = 0; mt < 2; mt++)
        #pragma unroll
        for (int j = 0; j < 8; j++)
            #pragma unroll
            for (int i = 0; i < 4; i++) c[mt][j][i] = 0.0f;

    for (int ki = 0; ki < 4; ki++) {
        const int buf = ki & 1;
        if (ki < 3) { CP_WAIT1(); } else { CP_WAIT0(); }
        __syncthreads();

        uint32_t a[2][4][4];
        #pragma unroll
        for (int mt = 0; mt < 2; mt++)
            #pragma unroll
            for (int kt = 0; kt < 4; kt++)
                ldsm4(a[mt][kt][0], a[mt][kt][1], a[mt][kt][2], a[mt][kt][3],
                      abase[buf] + (w * 32 + mt * 16 + ar) * 128
                                 + ((kt * 32 + ak) ^ axor));

        #pragma unroll
        for (int jj = 0; jj < 4; jj++) {
            #pragma unroll
            for (int kt = 0; kt < 4; kt++) {
                uint32_t r0, r1, r2, r3;
                ldsm4(r0, r1, r2, r3,
                      bbase[buf] + (jj * 16 + brow) * 128 + ((kt * 32 + bkb) ^ bxor));
                uint32_t blo[2] = { r0, r1 }, bhi[2] = { r2, r3 };
                mma16816(c[0][2 * jj],     a[0][kt], blo);
                mma16816(c[0][2 * jj + 1], a[0][kt], bhi);
                mma16816(c[1][2 * jj],     a[1][kt], blo);
                mma16816(c[1][2 * jj + 1], a[1][kt], bhi);
            }
        }
        __syncthreads();

        if (ki + 2 < 4) load_tiles(ki + 2, buf);
    }

    const int head = blockIdx.x;
    if (z != 2) {
        __nv_bfloat16* out = (z == 0) ? g_Qb : g_Kb;
        #pragma unroll
        for (int mt = 0; mt < 2; mt++) {
            int r0 = m0 + w * 32 + mt * 16 + g;
            #pragma unroll
            for (int half = 0; half < 2; half++) {
                int m  = r0 + half * 8;
                int b_ = m >> 11;
                int s_ = m & (SS - 1);
                int bh = b_ * NHH + head;
                #pragma unroll
                for (int j = 0; j < 8; j++) {
                    int d = 8 * j + 2 * tig;
                    float v0 = c[mt][j][half * 2 + 0] + bias[n0 + d];
                    float v1 = c[mt][j][half * 2 + 1] + bias[n0 + d + 1];
                    *(uint32_t*)&out[(bh * SS + s_) * HDD + d] = packbf(v0, v1);
                }
            }
        }
    } else {
        // V: write into Ts[d][s_local] (aliases A buffers), coalesced copy out
        __nv_bfloat16* Ts = (__nv_bfloat16*)qsm;
        #pragma unroll
        for (int mt = 0; mt < 2; mt++) {
            #pragma unroll
            for (int half = 0; half < 2; half++) {
                int sl = w * 32 + mt * 16 + g + half * 8;
                #pragma unroll
                for (int j = 0; j < 8; j++) {
                    int d = 8 * j + 2 * tig;
                    float v0 = c[mt][j][half * 2 + 0] + bias[n0 + d];
                    float v1 = c[mt][j][half * 2 + 1] + bias[n0 + d + 1];
                    Ts[d * 136 + sl]       = __float2bfloat16(v0);
                    Ts[(d + 1) * 136 + sl] = __float2bfloat16(v1);
                }
            }
        }
        __syncthreads();
        int d = t >> 1, half = t & 1;
        int b_ = m0 >> 11;
        int s0 = m0 & (SS - 1);
        int bh = b_ * NHH + head;
        const uint4* src = (const uint4*)&Ts[d * 136 + half * 64];
        uint4* dst = (uint4*)&g_Vt[((size_t)bh * HDD + d) * SS + s0 + half * 64];
        #pragma unroll
        for (int i = 0; i < 8; i++) dst[i] = src[i];
    }
}

// ---------------------------------------------------------------------------
// Kernel 2: flash attention (R7/R10/R11 verbatim — best known config).
// ---------------------------------------------------------------------------
#define NIT 32            // SS / 64
#define SM_K0   0
#define SM_K1   8192
#define SM_V0   16384
#define SM_V1   24576
#define SM_M0   32768
#define SM_M1   67584
#define MPITCH  68
#define ATTN_SMEM 102400

__global__ __launch_bounds__(128) void attn_kernel(const float* __restrict__ mask)
{
    extern __shared__ char dynsm[];

    const int t = threadIdx.x;
    const int w = t >> 5, lane = t & 31;
    const int g = lane >> 2, tig = lane & 3;
    const int bh = blockIdx.x;
    const int qb = blockIdx.y;
    const int b_ = bh >> 2;
    const int h_ = bh & 3;

    const uint32_t smb = smem_u32(dynsm);
    const uint32_t kbase[2] = { smb + SM_K0, smb + SM_K1 };
    const uint32_t vbase[2] = { smb + SM_V0, smb + SM_V1 };
    const uint32_t mbase[2] = { smb + SM_M0, smb + SM_M1 };
    float* const msm[2] = { (float*)(dynsm + SM_M0), (float*)(dynsm + SM_M1) };

    const __nv_bfloat16* Qg = g_Qb + (size_t)bh * SS * HDD;
    const char* Kg = (const char*)(g_Kb + (size_t)bh * SS * HDD);
    const char* Vg = (const char*)(g_Vt + (size_t)bh * HDD * SS);
    const float* Mb = mask + (size_t)b_ * SS * SS + (size_t)(qb * 128) * SS;

    int ld_src[4], ld_dst[4], ld_row[4];
    #pragma unroll
    for (int jc = 0; jc < 4; jc++) {
        int c = t + 128 * jc;
        int row = c >> 3, seg = c & 7;
        ld_row[jc] = row;
        ld_src[jc] = row * 128 + seg * 16;
        ld_dst[jc] = row * 128 + ((seg * 16) ^ ((row & 7) * 16));
    }
    int md_dst[16], md_row[16];
    #pragma unroll
    for (int jm = 0; jm < 16; jm++) {
        int c = t + 128 * jm;
        int row = c >> 4, seg = c & 15;
        md_row[jm] = row;
        md_dst[jm] = row * (MPITCH * 4) + seg * 16;
    }

    const int lrow = (lane & 7) | ((lane & 16) >> 1);
    const int lkb  = (lane & 8) ? 16 : 0;
    const int lxor = (lrow & 7) * 16;
    const int lbase = lrow * 128;

    const int qrow[2] = { qb * 128 + w * 32 + g, qb * 128 + w * 32 + 16 + g };
    uint32_t aq[2][4][4];
    #pragma unroll
    for (int mt = 0; mt < 2; mt++) {
        const __nv_bfloat16* r0 = Qg + (size_t)qrow[mt] * HDD;
        const __nv_bfloat16* r1 = r0 + 8 * HDD;
        #pragma unroll
        for (int kt = 0; kt < 4; kt++) {
            aq[mt][kt][0] = *(const uint32_t*)(r0 + kt * 16 + 2 * tig);
            aq[mt][kt][1] = *(const uint32_t*)(r1 + kt * 16 + 2 * tig);
            aq[mt][kt][2] = *(const uint32_t*)(r0 + kt * 16 + 2 * tig + 8);
            aq[mt][kt][3] = *(const uint32_t*)(r1 + kt * 16 + 2 * tig + 8);
        }
    }

    auto load_tiles = [&](int it, int buf) {
        const char* Ks = Kg + (size_t)it * 64 * 128;
        #pragma unroll
        for (int jc = 0; jc < 4; jc++) {
            cp16(kbase[buf] + ld_dst[jc], Ks + ld_src[jc]);
            cp16(vbase[buf] + ld_dst[jc],
                 Vg + (size_t)ld_row[jc] * (SS * 2) + it * 128 + (t & 7) * 16);
        }
        #pragma unroll
        for (int jm = 0; jm < 16; jm++) {
            cp16(mbase[buf] + md_dst[jm],
                 (const char*)(Mb + (size_t)md_row[jm] * SS + it * 64) + (t & 15) * 16);
        }
        CP_COMMIT();
    };

    load_tiles(0, 0);
    load_tiles(1, 1);

    float o[2][8][4];
    #pragma unroll
    for (int mt = 0; mt < 2; mt++)
        #pragma unroll
        for (int j = 0; j < 8; j++)
            #pragma unroll
            for (int i = 0; i < 4; i++) o[mt][j][i] = 0.0f;
    float lacc[2][2] = {{0.0f, 0.0f}, {0.0f, 0.0f}};

    for (int i = 0; i < NIT; i++) {
        const int buf = i & 1;
        if (i < NIT - 1) { CP_WAIT1(); } else { CP_WAIT0(); }
        __syncthreads();

        float c[2][8][4];
        #pragma unroll
        for (int mt = 0; mt < 2; mt++)
            #pragma unroll
            for (int j = 0; j < 8; j++)
                #pragma unroll
                for (int q = 0; q < 4; q++) c[mt][j][q] = 0.0f;

        #pragma unroll
        for (int jj = 0; jj < 4; jj++) {
            #pragma unroll
            for (int kt = 0; kt < 4; kt++) {
                uint32_t r0, r1, r2, r3;
                ldsm4(r0, r1, r2, r3,
                      kbase[buf] + jj * 2048 + lbase + ((kt * 32 + lkb) ^ lxor));
                uint32_t blo[2] = { r0, r1 }, bhi[2] = { r2, r3 };
                mma16816(c[0][2 * jj],     aq[0][kt], blo);
                mma16816(c[0][2 * jj + 1], aq[0][kt], bhi);
                mma16816(c[1][2 * jj],     aq[1][kt], blo);
                mma16816(c[1][2 * jj + 1], aq[1][kt], bhi);
            }
        }

        uint32_t pa[2][4][4];
        #pragma unroll
        for (int mt = 0; mt < 2; mt++) {
            const float* mp0 = msm[buf] + (w * 32 + mt * 16 + g) * MPITCH + 2 * tig;
            const float* mp1 = mp0 + 8 * MPITCH;
            #pragma unroll
            for (int j = 0; j < 8; j++) {
                float2 mk0 = *(const float2*)(mp0 + 8 * j);
                float2 mk1 = *(const float2*)(mp1 + 8 * j);
                float p0 = __expf(fmaf(c[mt][j][0], 0.125f, mk0.x));
                float p1 = __expf(fmaf(c[mt][j][1], 0.125f, mk0.y));
                float p2 = __expf(fmaf(c[mt][j][2], 0.125f, mk1.x));
                float p3 = __expf(fmaf(c[mt][j][3], 0.125f, mk1.y));
                lacc[mt][0] += p0 + p1;
                lacc[mt][1] += p2 + p3;
                int kt = j >> 1, hi = (j & 1) * 2;
                pa[mt][kt][hi + 0] = packbf(p0, p1);
                pa[mt][kt][hi + 1] = packbf(p2, p3);
            }
        }

        #pragma unroll
        for (int jj = 0; jj < 4; jj++) {
            #pragma unroll
            for (int kt = 0; kt < 4; kt++) {
                uint32_t r0, r1, r2, r3;
                ldsm4(r0, r1, r2, r3,
                      vbase[buf] + jj * 2048 + lbase + ((kt * 32 + lkb) ^ lxor));
                uint32_t blo[2] = { r0, r1 }, bhi[2] = { r2, r3 };
                mma16816(o[0][2 * jj],     pa[0][kt], blo);
                mma16816(o[0][2 * jj + 1], pa[0][kt], bhi);
                mma16816(o[1][2 * jj],     pa[1][kt], blo);
                mma16816(o[1][2 * jj + 1], pa[1][kt], bhi);
            }
        }

        __syncthreads();

        if (i + 2 < NIT) load_tiles(i + 2, buf);
    }

    #pragma unroll
    for (int mt = 0; mt < 2; mt++)
        #pragma unroll
        for (int h = 0; h < 2; h++) {
            float v = lacc[mt][h];
            v += __shfl_xor_sync(0xffffffffu, v, 1);
            v += __shfl_xor_sync(0xffffffffu, v, 2);
            lacc[mt][h] = 1.0f / v;
        }

    #pragma unroll
    for (int mt = 0; mt < 2; mt++) {
        __nv_bfloat16* c0 = g_ctxb + ((size_t)b_ * SS + qrow[mt]) * HH + h_ * HDD;
        __nv_bfloat16* c1 = c0 + 8 * HH;
        #pragma unroll
        for (int j = 0; j < 8; j++) {
            int d = 8 * j + 2 * tig;
            *(uint32_t*)(c0 + d) = packbf(o[mt][j][0] * lacc[mt][0],
                                          o[mt][j][1] * lacc[mt][0]);
            *(uint32_t*)(c1 + d) = packbf(o[mt][j][2] * lacc[mt][1],
                                          o[mt][j][3] * lacc[mt][1]);
        }
    }
}

// ---------------------------------------------------------------------------
// Kernel 3: out projection + residual + LayerNorm fused — all-bf16 staging.
// BM=64, BN=256, BK=64 (4 iters), cp.async double-buffered.
// Dynamic smem 81920 B: A0@0, A1@8192, B0@16384, B1@49152.
// ---------------------------------------------------------------------------
#define PSM_A0 0
#define PSM_A1 8192
#define PSM_B0 16384
#define PSM_B1 49152
#define PLN_SMEM 81920

__global__ __launch_bounds__(128) void projln_kernel(
    const float* __restrict__ X,
    const float* __restrict__ bo,
    const float* __restrict__ gamma, const float* __restrict__ beta,
    float* __restrict__ out)
{
    extern __shared__ char psm[];
    __shared__ float sgb[256 * 3];            // gamma | beta | bo

    const int t = threadIdx.x;
    const int w = t >> 5, lane = t & 31;
    const int g = lane >> 2, tig = lane & 3;
    const int m0 = blockIdx.x * 64;

    const uint32_t smb = smem_u32(psm);
    const uint32_t abase[2] = { smb + PSM_A0, smb + PSM_A1 };
    const uint32_t bbase[2] = { smb + PSM_B0, smb + PSM_B1 };

    const char* Ca = (const char*)g_ctxb + (size_t)m0 * 512;
    const char* Wa = (const char*)g_Wto;

    const int ar   = (lane & 7) + ((lane & 8) ? 8 : 0);
    const int ak   = (lane & 16) ? 16 : 0;
    const int axor = (lane & 7) * 16;
    const int brow = (lane & 7) | ((lane & 16) >> 1);
    const int bkb  = (lane & 8) ? 16 : 0;
    const int bxor = (brow & 7) * 16;

    sgb[t]             = gamma[t];
    sgb[t + 128]       = gamma[t + 128];
    sgb[256 + t]       = beta[t];
    sgb[256 + t + 128] = beta[t + 128];
    sgb[512 + t]       = bo[t];
    sgb[512 + t + 128] = bo[t + 128];

    auto load_tiles = [&](int ki, int buf) {
        const int kb = ki * 128;
        #pragma unroll
        for (int j = 0; j < 4; j++) {            // A: 512 chunks (64 rows)
            int c = t + 128 * j;
            int row = c >> 3, seg = c & 7;
            cp16(abase[buf] + row * 128 + ((seg * 16) ^ ((row & 7) * 16)),
                 Ca + (size_t)row * 512 + kb + seg * 16);
        }
        #pragma unroll
        for (int j = 0; j < 16; j++) {           // B: 2048 chunks (256 rows)
            int c = t + 128 * j;
            int row = c >> 3, seg = c & 7;
            cp16(bbase[buf] + row * 128 + ((seg * 16) ^ ((row & 7) * 16)),
                 Wa + (size_t)row * 512 + kb + seg * 16);
        }
        CP_COMMIT();
    };

    load_tiles(0, 0);
    load_tiles(1, 1);

    float c[32][4];
    #pragma unroll
    for (int j = 0; j < 32; j++)
        #pragma unroll
        for (int i = 0; i < 4; i++) c[j][i] = 0.0f;

    for (int ki = 0; ki < 4; ki++) {
        const int buf = ki & 1;
        if (ki < 3) { CP_WAIT1(); } else { CP_WAIT0(); }
        __syncthreads();

        uint32_t a[4][4];
        #pragma unroll
        for (int kt = 0; kt < 4; kt++)
            ldsm4(a[kt][0], a[kt][1], a[kt][2], a[kt][3],
                  abase[buf] + (w * 16 + ar) * 128 + ((kt * 32 + ak) ^ axor));

        #pragma unroll
        for (int jp = 0; jp < 16; jp++) {
            #pragma unroll
            for (int kt = 0; kt < 4; kt++) {
                uint32_t r0, r1, r2, r3;
                ldsm4(r0, r1, r2, r3,
                      bbase[buf] + (jp * 16 + brow) * 128 + ((kt * 32 + bkb) ^ bxor));
                uint32_t blo[2] = { r0, r1 }, bhi[2] = { r2, r3 };
                mma16816(c[2 * jp],     a[kt], blo);
                mma16816(c[2 * jp + 1], a[kt], bhi);
            }
        }
        __syncthreads();

        if (ki + 2 < 4) load_tiles(ki + 2, buf);
    }

    // ---- epilogue: + bo + X, then LN over each full row ----
    const int r0g = m0 + w * 16 + g;
    float sum0 = 0.0f, sum1 = 0.0f;
    #pragma unroll
    for (int j = 0; j < 32; j++) {
        int n = 8 * j + 2 * tig;
        float2 x0 = *(const float2*)(X + (size_t)r0g * HH + n);
        float2 x1 = *(const float2*)(X + (size_t)(r0g + 8) * HH + n);
        float b0 = sgb[512 + n], b1 = sgb[512 + n + 1];
        c[j][0] += b0 + x0.x;
        c[j][1] += b1 + x0.y;
        c[j][2] += b0 + x1.x;
        c[j][3] += b1 + x1.y;
        sum0 += c[j][0] + c[j][1];
        sum1 += c[j][2] + c[j][3];
    }
    sum0 += __shfl_xor_sync(0xffffffffu, sum0, 1);
    sum0 += __shfl_xor_sync(0xffffffffu, sum0, 2);
    sum1 += __shfl_xor_sync(0xffffffffu, sum1, 1);
    sum1 += __shfl_xor_sync(0xffffffffu, sum1, 2);
    float mu0 = sum0 * (1.0f / 256.0f);
    float mu1 = sum1 * (1.0f / 256.0f);

    float vs0 = 0.0f, vs1 = 0.0f;
    #pragma unroll
    for (int j = 0; j < 32; j++) {
        float d0 = c[j][0] - mu0, d1 = c[j][1] - mu0;
        float d2 = c[j][2] - mu1, d3 = c[j][3] - mu1;
        vs0 += d0 * d0 + d1 * d1;
        vs1 += d2 * d2 + d3 * d3;
    }
    vs0 += __shfl_xor_sync(0xffffffffu, vs0, 1);
    vs0 += __shfl_xor_sync(0xffffffffu, vs0, 2);
    vs1 += __shfl_xor_sync(0xffffffffu, vs1, 1);
    vs1 += __shfl_xor_sync(0xffffffffu, vs1, 2);
    float inv0 = rsqrtf(vs0 * (1.0f / 256.0f) + 1e-12f);
    float inv1 = rsqrtf(vs1 * (1.0f / 256.0f) + 1e-12f);

    #pragma unroll
    for (int j = 0; j < 32; j++) {
        int n = 8 * j + 2 * tig;
        float ga0 = sgb[n], ga1 = sgb[n + 1];
        float be0 = sgb[256 + n], be1 = sgb[256 + n + 1];
        float2 o0, o1;
        o0.x = (c[j][0] - mu0) * inv0 * ga0 + be0;
        o0.y = (c[j][1] - mu0) * inv0 * ga1 + be1;
        o1.x = (c[j][2] - mu1) * inv1 * ga0 + be0;
        o1.y = (c[j][3] - mu1) * inv1 * ga1 + be1;
        *(float2*)(out + (size_t)r0g * HH + n)       = o0;
        *(float2*)(out + (size_t)(r0g + 8) * HH + n) = o1;
    }
}

// ---------------------------------------------------------------------------
extern "C" void kernel_launch(void* const* d_in, const int* in_sizes, int n_in,
                              void* d_out, int out_size)
{
    const float* X     = (const float*)d_in[0];
    const float* mask  = (const float*)d_in[1];
    const float* Wq    = (const float*)d_in[2];
    const float* bq    = (const float*)d_in[3];
    const float* Wk    = (const float*)d_in[4];
    const float* bk    = (const float*)d_in[5];
    const float* Wv    = (const float*)d_in[6];
    const float* bv    = (const float*)d_in[7];
    const float* Wo    = (const float*)d_in[8];
    const float* bo    = (const float*)d_in[9];
    const float* gamma = (const float*)d_in[10];
    const float* beta  = (const float*)d_in[11];
    float* out = (float*)d_out;

    cudaFuncSetAttribute(attn_kernel,
                         cudaFuncAttributeMaxDynamicSharedMemorySize, ATTN_SMEM);
    cudaFuncSetAttribute(qkv_kernel,
                         cudaFuncAttributeMaxDynamicSharedMemorySize, QKV_SMEM);
    cudaFuncSetAttribute(projln_kernel,
                         cudaFuncAttributeMaxDynamicSharedMemorySize, PLN_SMEM);

    cvt_x_kernel<<<MTOT * HH / 2048, 256>>>(X);
    cvt_w_kernel<<<dim3(HH / 32, HH / 32, 4), 256>>>(Wq, Wk, Wv, Wo);
    qkv_kernel<<<dim3(HH / 64, MTOT / 128, 3), 128, QKV_SMEM>>>(bq, bk, bv);
    attn_kernel<<<dim3(BB * NHH, SS / 128), 128, ATTN_SMEM>>>(mask);
    projln_kernel<<<MTOT / 64, 128, PLN_SMEM>>>(X, bo, gamma, beta, out);
}

// round 13
// speedup vs baseline: 1.4673x; 1.0726x over previous
#include <cuda_runtime.h>
#include <cuda_bf16.h>
#include <stdint.h>
#include <math.h>

#define BB   8
#define SS   2048
#define HH   256
#define NHH  4
#define HDD  64
#define MTOT (BB * SS)   // 16384

// ---------------------------------------------------------------------------
// Scratch (__device__ globals only).
// ---------------------------------------------------------------------------
__device__ __align__(128) __nv_bfloat16 g_Xb[MTOT * HH];       // X in bf16
__device__ __align__(128) __nv_bfloat16 g_Wtq[HH * HH];        // W^T bf16 [n][k]
__device__ __align__(128) __nv_bfloat16 g_Wtk[HH * HH];
__device__ __align__(128) __nv_bfloat16 g_Wtv[HH * HH];
__device__ __align__(128) __nv_bfloat16 g_Wto[HH * HH];
__device__ __align__(128) __nv_bfloat16 g_Qb[32 * SS * HDD];   // [bh][s][d]
__device__ __align__(128) __nv_bfloat16 g_Kb[32 * SS * HDD];   // [bh][s][d]
__device__ __align__(128) __nv_bfloat16 g_Vt[32 * HDD * SS];   // [bh][d][s]
__device__ __align__(128) __nv_bfloat16 g_ctxb[MTOT * HH];     // [m][h*64+d]

// ---------------------------------------------------------------------------
// Helpers
// ---------------------------------------------------------------------------
__device__ __forceinline__ uint32_t packbf(float lo, float hi) {
    uint32_t r;
    asm("cvt.rn.bf16x2.f32 %0, %1, %2;" : "=r"(r) : "f"(hi), "f"(lo));
    return r;
}

__device__ __forceinline__ void mma16816(float* c, const uint32_t* a, const uint32_t* b) {
    asm volatile(
        "mma.sync.aligned.m16n8k16.row.col.f32.bf16.bf16.f32 "
        "{%0,%1,%2,%3}, {%4,%5,%6,%7}, {%8,%9}, {%0,%1,%2,%3};\n"
        : "+f"(c[0]), "+f"(c[1]), "+f"(c[2]), "+f"(c[3])
        : "r"(a[0]), "r"(a[1]), "r"(a[2]), "r"(a[3]), "r"(b[0]), "r"(b[1]));
}

__device__ __forceinline__ uint32_t smem_u32(const void* p) {
    uint32_t a;
    asm("{ .reg .u64 t; cvta.to.shared.u64 t, %1; cvt.u32.u64 %0, t; }" : "=r"(a) : "l"(p));
    return a;
}

__device__ __forceinline__ void ldsm4(uint32_t& r0, uint32_t& r1, uint32_t& r2, uint32_t& r3,
                                      uint32_t addr) {
    asm volatile("ldmatrix.sync.aligned.m8n8.x4.shared.b16 {%0,%1,%2,%3}, [%4];"
                 : "=r"(r0), "=r"(r1), "=r"(r2), "=r"(r3) : "r"(addr));
}

__device__ __forceinline__ void cp16(uint32_t dst, const void* src) {
    asm volatile("cp.async.cg.shared.global [%0], [%1], 16;" :: "r"(dst), "l"(src));
}
#define CP_COMMIT() asm volatile("cp.async.commit_group;" ::: "memory")
#define CP_WAIT1()  asm volatile("cp.async.wait_group 1;" ::: "memory")
#define CP_WAIT0()  asm volatile("cp.async.wait_group 0;" ::: "memory")

// ---------------------------------------------------------------------------
// Kernel 0a: X fp32 -> bf16
// ---------------------------------------------------------------------------
__global__ __launch_bounds__(256) void cvt_x_kernel(const float* __restrict__ X)
{
    int idx = (blockIdx.x * 256 + threadIdx.x) * 8;
    float4 v0 = *(const float4*)(X + idx);
    float4 v1 = *(const float4*)(X + idx + 4);
    uint4 o;
    o.x = packbf(v0.x, v0.y);
    o.y = packbf(v0.z, v0.w);
    o.z = packbf(v1.x, v1.y);
    o.w = packbf(v1.z, v1.w);
    *(uint4*)&g_Xb[idx] = o;
}

// ---------------------------------------------------------------------------
// Kernel 0b: W fp32 [k][n] -> bf16 transposed [n][k]  (32x32 smem transpose)
// ---------------------------------------------------------------------------
__global__ __launch_bounds__(256) void cvt_w_kernel(
    const float* __restrict__ Wq, const float* __restrict__ Wk,
    const float* __restrict__ Wv, const float* __restrict__ Wo)
{
    __shared__ float sm[32][33];
    const float* W;  __nv_bfloat16* out;
    if (blockIdx.z == 0)      { W = Wq; out = g_Wtq; }
    else if (blockIdx.z == 1) { W = Wk; out = g_Wtk; }
    else if (blockIdx.z == 2) { W = Wv; out = g_Wtv; }
    else                      { W = Wo; out = g_Wto; }

    const int k0 = blockIdx.x * 32, n0 = blockIdx.y * 32;
    const int x = threadIdx.x & 31, y = threadIdx.x >> 5;
    #pragma unroll
    for (int i = 0; i < 4; i++) {
        int r = y + 8 * i;
        sm[r][x] = W[(k0 + r) * HH + n0 + x];
    }
    __syncthreads();
    #pragma unroll
    for (int i = 0; i < 4; i++) {
        int nr = y + 8 * i;
        out[(n0 + nr) * HH + k0 + x] = __float2bfloat16(sm[x][nr]);
    }
}

// ---------------------------------------------------------------------------
// Kernel 1: QKV projection — all-bf16, cp.async double-buffered, ldmatrix.
// (unchanged from R12)
// ---------------------------------------------------------------------------
#define QSM_A0 0
#define QSM_A1 16384
#define QSM_B0 32768
#define QSM_B1 40960
#define QKV_SMEM 49152

__global__ __launch_bounds__(128) void qkv_kernel(
    const float* __restrict__ bq, const float* __restrict__ bk,
    const float* __restrict__ bv)
{
    extern __shared__ char qsm[];

    const int z = blockIdx.z;
    const __nv_bfloat16* Wt;  const float* bias;
    if (z == 0)      { Wt = g_Wtq; bias = bq; }
    else if (z == 1) { Wt = g_Wtk; bias = bk; }
    else             { Wt = g_Wtv; bias = bv; }

    const int t = threadIdx.x;
    const int w = t >> 5, lane = t & 31;
    const int g = lane >> 2, tig = lane & 3;
    const int m0 = blockIdx.y * 128, n0 = blockIdx.x * 64;

    const uint32_t smb = smem_u32(qsm);
    const uint32_t abase[2] = { smb + QSM_A0, smb + QSM_A1 };
    const uint32_t bbase[2] = { smb + QSM_B0, smb + QSM_B1 };

    const char* Xa = (const char*)g_Xb + (size_t)m0 * 512;
    const char* Wa = (const char*)Wt  + (size_t)n0 * 512;

    const int ar   = (lane & 7) + ((lane & 8) ? 8 : 0);
    const int ak   = (lane & 16) ? 16 : 0;
    const int axor = (lane & 7) * 16;
    const int brow = (lane & 7) | ((lane & 16) >> 1);
    const int bkb  = (lane & 8) ? 16 : 0;
    const int bxor = (brow & 7) * 16;

    auto load_tiles = [&](int ki, int buf) {
        const int kb = ki * 128;
        #pragma unroll
        for (int j = 0; j < 8; j++) {
            int c = t + 128 * j;
            int row = c >> 3, seg = c & 7;
            cp16(abase[buf] + row * 128 + ((seg * 16) ^ ((row & 7) * 16)),
                 Xa + (size_t)row * 512 + kb + seg * 16);
        }
        #pragma unroll
        for (int j = 0; j < 4; j++) {
            int c = t + 128 * j;
            int row = c >> 3, seg = c & 7;
            cp16(bbase[buf] + row * 128 + ((seg * 16) ^ ((row & 7) * 16)),
                 Wa + (size_t)row * 512 + kb + seg * 16);
        }
        CP_COMMIT();
    };

    load_tiles(0, 0);
    load_tiles(1, 1);

    float c[2][8][4];
    #pragma unroll
    for (int mt = 0; mt < 2; mt++)
        #pragma unroll
        for (int j = 0; j < 8; j++)
            #pragma unroll
            for (int i = 0; i < 4; i++) c[mt][j][i] = 0.0f;

    for (int ki = 0; ki < 4; ki++) {
        const int buf = ki & 1;
        if (ki < 3) { CP_WAIT1(); } else { CP_WAIT0(); }
        __syncthreads();

        uint32_t a[2][4][4];
        #pragma unroll
        for (int mt = 0; mt < 2; mt++)
            #pragma unroll
            for (int kt = 0; kt < 4; kt++)
                ldsm4(a[mt][kt][0], a[mt][kt][1], a[mt][kt][2], a[mt][kt][3],
                      abase[buf] + (w * 32 + mt * 16 + ar) * 128
                                 + ((kt * 32 + ak) ^ axor));

        #pragma unroll
        for (int jj = 0; jj < 4; jj++) {
            #pragma unroll
            for (int kt = 0; kt < 4; kt++) {
                uint32_t r0, r1, r2, r3;
                ldsm4(r0, r1, r2, r3,
                      bbase[buf] + (jj * 16 + brow) * 128 + ((kt * 32 + bkb) ^ bxor));
                uint32_t blo[2] = { r0, r1 }, bhi[2] = { r2, r3 };
                mma16816(c[0][2 * jj],     a[0][kt], blo);
                mma16816(c[0][2 * jj + 1], a[0][kt], bhi);
                mma16816(c[1][2 * jj],     a[1][kt], blo);
                mma16816(c[1][2 * jj + 1], a[1][kt], bhi);
            }
        }
        __syncthreads();

        if (ki + 2 < 4) load_tiles(ki + 2, buf);
    }

    const int head = blockIdx.x;
    if (z != 2) {
        __nv_bfloat16* out = (z == 0) ? g_Qb : g_Kb;
        #pragma unroll
        for (int mt = 0; mt < 2; mt++) {
            int r0 = m0 + w * 32 + mt * 16 + g;
            #pragma unroll
            for (int half = 0; half < 2; half++) {
                int m  = r0 + half * 8;
                int b_ = m >> 11;
                int s_ = m & (SS - 1);
                int bh = b_ * NHH + head;
                #pragma unroll
                for (int j = 0; j < 8; j++) {
                    int d = 8 * j + 2 * tig;
                    float v0 = c[mt][j][half * 2 + 0] + bias[n0 + d];
                    float v1 = c[mt][j][half * 2 + 1] + bias[n0 + d + 1];
                    *(uint32_t*)&out[(bh * SS + s_) * HDD + d] = packbf(v0, v1);
                }
            }
        }
    } else {
        __nv_bfloat16* Ts = (__nv_bfloat16*)qsm;
        #pragma unroll
        for (int mt = 0; mt < 2; mt++) {
            #pragma unroll
            for (int half = 0; half < 2; half++) {
                int sl = w * 32 + mt * 16 + g + half * 8;
                #pragma unroll
                for (int j = 0; j < 8; j++) {
                    int d = 8 * j + 2 * tig;
                    float v0 = c[mt][j][half * 2 + 0] + bias[n0 + d];
                    float v1 = c[mt][j][half * 2 + 1] + bias[n0 + d + 1];
                    Ts[d * 136 + sl]       = __float2bfloat16(v0);
                    Ts[(d + 1) * 136 + sl] = __float2bfloat16(v1);
                }
            }
        }
        __syncthreads();
        int d = t >> 1, half = t & 1;
        int b_ = m0 >> 11;
        int s0 = m0 & (SS - 1);
        int bh = b_ * NHH + head;
        const uint4* src = (const uint4*)&Ts[d * 136 + half * 64];
        uint4* dst = (uint4*)&g_Vt[((size_t)bh * HDD + d) * SS + s0 + half * 64];
        #pragma unroll
        for (int i = 0; i < 8; i++) dst[i] = src[i];
    }
}

// ---------------------------------------------------------------------------
// Kernel 2: flash attention — R12 structure with addressing state inlined
// (frees ~44 registers held only for the cp.async loader).
// ---------------------------------------------------------------------------
#define NIT 32            // SS / 64
#define SM_K0   0
#define SM_K1   8192
#define SM_V0   16384
#define SM_V1   24576
#define SM_M0   32768
#define SM_M1   67584
#define MPITCH  68
#define ATTN_SMEM 102400

__global__ __launch_bounds__(128) void attn_kernel(const float* __restrict__ mask)
{
    extern __shared__ char dynsm[];

    const int t = threadIdx.x;
    const int w = t >> 5, lane = t & 31;
    const int g = lane >> 2, tig = lane & 3;
    const int bh = blockIdx.x;
    const int qb = blockIdx.y;
    const int b_ = bh >> 2;
    const int h_ = bh & 3;

    const uint32_t smb = smem_u32(dynsm);

    const __nv_bfloat16* Qg = g_Qb + (size_t)bh * SS * HDD;
    const char* Kg = (const char*)(g_Kb + (size_t)bh * SS * HDD);
    const char* Vg = (const char*)(g_Vt + (size_t)bh * HDD * SS);
    const float* Mb = mask + (size_t)b_ * SS * SS + (size_t)(qb * 128) * SS;

    // ldmatrix addressing (B-frags for both S and PV loops)
    const int lrow = (lane & 7) | ((lane & 16) >> 1);
    const int lkb  = (lane & 8) ? 16 : 0;
    const int lxor = (lrow & 7) * 16;
    const int lbase = lrow * 128;

    // Q A-fragments (2 m-tiles of 16 rows), resident all iterations
    const int qrow[2] = { qb * 128 + w * 32 + g, qb * 128 + w * 32 + 16 + g };
    uint32_t aq[2][4][4];
    #pragma unroll
    for (int mt = 0; mt < 2; mt++) {
        const __nv_bfloat16* r0 = Qg + (size_t)qrow[mt] * HDD;
        const __nv_bfloat16* r1 = r0 + 8 * HDD;
        #pragma unroll
        for (int kt = 0; kt < 4; kt++) {
            aq[mt][kt][0] = *(const uint32_t*)(r0 + kt * 16 + 2 * tig);
            aq[mt][kt][1] = *(const uint32_t*)(r1 + kt * 16 + 2 * tig);
            aq[mt][kt][2] = *(const uint32_t*)(r0 + kt * 16 + 2 * tig + 8);
            aq[mt][kt][3] = *(const uint32_t*)(r1 + kt * 16 + 2 * tig + 8);
        }
    }

    // Tile loader: all addressing recomputed inline (no persistent arrays).
    auto load_tiles = [&](int it, int buf) {
        const uint32_t kb = smb + (buf ? SM_K1 : SM_K0);
        const uint32_t vb = smb + (buf ? SM_V1 : SM_V0);
        const uint32_t mb = smb + (buf ? SM_M1 : SM_M0);
        const char* Ks = Kg + (size_t)it * 64 * 128;
        #pragma unroll
        for (int jc = 0; jc < 4; jc++) {
            int c = t + 128 * jc;
            int row = c >> 3, seg = c & 7;
            uint32_t dst = row * 128 + ((seg * 16) ^ ((row & 7) * 16));
            cp16(kb + dst, Ks + row * 128 + seg * 16);
            cp16(vb + dst, Vg + (size_t)row * (SS * 2) + it * 128 + seg * 16);
        }
        #pragma unroll
        for (int jm = 0; jm < 16; jm++) {
            int c = t + 128 * jm;
            int row = c >> 4, seg = c & 15;
            cp16(mb + row * (MPITCH * 4) + seg * 16,
                 (const char*)(Mb + (size_t)row * SS + it * 64) + seg * 16);
        }
        CP_COMMIT();
    };

    load_tiles(0, 0);
    load_tiles(1, 1);

    float o[2][8][4];
    #pragma unroll
    for (int mt = 0; mt < 2; mt++)
        #pragma unroll
        for (int j = 0; j < 8; j++)
            #pragma unroll
            for (int i = 0; i < 4; i++) o[mt][j][i] = 0.0f;
    float lacc[2][2] = {{0.0f, 0.0f}, {0.0f, 0.0f}};

    for (int i = 0; i < NIT; i++) {
        const int buf = i & 1;
        const uint32_t kb = smb + (buf ? SM_K1 : SM_K0);
        const uint32_t vb = smb + (buf ? SM_V1 : SM_V0);
        const float* msm = (const float*)(dynsm + (buf ? SM_M1 : SM_M0));

        if (i < NIT - 1) { CP_WAIT1(); } else { CP_WAIT0(); }
        __syncthreads();

        // ---- S = Q @ K^T ----
        float c[2][8][4];
        #pragma unroll
        for (int mt = 0; mt < 2; mt++)
            #pragma unroll
            for (int j = 0; j < 8; j++)
                #pragma unroll
                for (int q = 0; q < 4; q++) c[mt][j][q] = 0.0f;

        #pragma unroll
        for (int jj = 0; jj < 4; jj++) {
            #pragma unroll
            for (int kt = 0; kt < 4; kt++) {
                uint32_t r0, r1, r2, r3;
                ldsm4(r0, r1, r2, r3,
                      kb + jj * 2048 + lbase + ((kt * 32 + lkb) ^ lxor));
                uint32_t blo[2] = { r0, r1 }, bhi[2] = { r2, r3 };
                mma16816(c[0][2 * jj],     aq[0][kt], blo);
                mma16816(c[0][2 * jj + 1], aq[0][kt], bhi);
                mma16816(c[1][2 * jj],     aq[1][kt], blo);
                mma16816(c[1][2 * jj + 1], aq[1][kt], bhi);
            }
        }

        // ---- softmax (no max): p = exp(s/8 + mask), mask from SMEM ----
        uint32_t pa[2][4][4];
        #pragma unroll
        for (int mt = 0; mt < 2; mt++) {
            const float* mp0 = msm + (w * 32 + mt * 16 + g) * MPITCH + 2 * tig;
            const float* mp1 = mp0 + 8 * MPITCH;
            #pragma unroll
            for (int j = 0; j < 8; j++) {
                float2 mk0 = *(const float2*)(mp0 + 8 * j);
                float2 mk1 = *(const float2*)(mp1 + 8 * j);
                float p0 = __expf(fmaf(c[mt][j][0], 0.125f, mk0.x));
                float p1 = __expf(fmaf(c[mt][j][1], 0.125f, mk0.y));
                float p2 = __expf(fmaf(c[mt][j][2], 0.125f, mk1.x));
                float p3 = __expf(fmaf(c[mt][j][3], 0.125f, mk1.y));
                lacc[mt][0] += p0 + p1;
                lacc[mt][1] += p2 + p3;
                int kt = j >> 1, hi = (j & 1) * 2;
                pa[mt][kt][hi + 0] = packbf(p0, p1);
                pa[mt][kt][hi + 1] = packbf(p2, p3);
            }
        }

        // ---- O += P @ V (V tile is [d][kv], non-trans ldmatrix) ----
        #pragma unroll
        for (int jj = 0; jj < 4; jj++) {
            #pragma unroll
            for (int kt = 0; kt < 4; kt++) {
                uint32_t r0, r1, r2, r3;
                ldsm4(r0, r1, r2, r3,
                      vb + jj * 2048 + lbase + ((kt * 32 + lkb) ^ lxor));
                uint32_t blo[2] = { r0, r1 }, bhi[2] = { r2, r3 };
                mma16816(o[0][2 * jj],     pa[0][kt], blo);
                mma16816(o[0][2 * jj + 1], pa[0][kt], bhi);
                mma16816(o[1][2 * jj],     pa[1][kt], blo);
                mma16816(o[1][2 * jj + 1], pa[1][kt], bhi);
            }
        }

        __syncthreads();

        if (i + 2 < NIT) load_tiles(i + 2, buf);
    }

    #pragma unroll
    for (int mt = 0; mt < 2; mt++)
        #pragma unroll
        for (int h = 0; h < 2; h++) {
            float v = lacc[mt][h];
            v += __shfl_xor_sync(0xffffffffu, v, 1);
            v += __shfl_xor_sync(0xffffffffu, v, 2);
            lacc[mt][h] = 1.0f / v;
        }

    #pragma unroll
    for (int mt = 0; mt < 2; mt++) {
        __nv_bfloat16* c0 = g_ctxb + ((size_t)b_ * SS + qrow[mt]) * HH + h_ * HDD;
        __nv_bfloat16* c1 = c0 + 8 * HH;
        #pragma unroll
        for (int j = 0; j < 8; j++) {
            int d = 8 * j + 2 * tig;
            *(uint32_t*)(c0 + d) = packbf(o[mt][j][0] * lacc[mt][0],
                                          o[mt][j][1] * lacc[mt][0]);
            *(uint32_t*)(c1 + d) = packbf(o[mt][j][2] * lacc[mt][1],
                                          o[mt][j][3] * lacc[mt][1]);
        }
    }
}

// ---------------------------------------------------------------------------
// Kernel 3: out projection + residual + LayerNorm fused (unchanged from R12).
// ---------------------------------------------------------------------------
#define PSM_A0 0
#define PSM_A1 8192
#define PSM_B0 16384
#define PSM_B1 49152
#define PLN_SMEM 81920

__global__ __launch_bounds__(128) void projln_kernel(
    const float* __restrict__ X,
    const float* __restrict__ bo,
    const float* __restrict__ gamma, const float* __restrict__ beta,
    float* __restrict__ out)
{
    extern __shared__ char psm[];
    __shared__ float sgb[256 * 3];

    const int t = threadIdx.x;
    const int w = t >> 5, lane = t & 31;
    const int g = lane >> 2, tig = lane & 3;
    const int m0 = blockIdx.x * 64;

    const uint32_t smb = smem_u32(psm);
    const uint32_t abase[2] = { smb + PSM_A0, smb + PSM_A1 };
    const uint32_t bbase[2] = { smb + PSM_B0, smb + PSM_B1 };

    const char* Ca = (const char*)g_ctxb + (size_t)m0 * 512;
    const char* Wa = (const char*)g_Wto;

    const int ar   = (lane & 7) + ((lane & 8) ? 8 : 0);
    const int ak   = (lane & 16) ? 16 : 0;
    const int axor = (lane & 7) * 16;
    const int brow = (lane & 7) | ((lane & 16) >> 1);
    const int bkb  = (lane & 8) ? 16 : 0;
    const int bxor = (brow & 7) * 16;

    sgb[t]             = gamma[t];
    sgb[t + 128]       = gamma[t + 128];
    sgb[256 + t]       = beta[t];
    sgb[256 + t + 128] = beta[t + 128];
    sgb[512 + t]       = bo[t];
    sgb[512 + t + 128] = bo[t + 128];

    auto load_tiles = [&](int ki, int buf) {
        const int kb = ki * 128;
        #pragma unroll
        for (int j = 0; j < 4; j++) {
            int c = t + 128 * j;
            int row = c >> 3, seg = c & 7;
            cp16(abase[buf] + row * 128 + ((seg * 16) ^ ((row & 7) * 16)),
                 Ca + (size_t)row * 512 + kb + seg * 16);
        }
        #pragma unroll
        for (int j = 0; j < 16; j++) {
            int c = t + 128 * j;
            int row = c >> 3, seg = c & 7;
            cp16(bbase[buf] + row * 128 + ((seg * 16) ^ ((row & 7) * 16)),
                 Wa + (size_t)row * 512 + kb + seg * 16);
        }
        CP_COMMIT();
    };

    load_tiles(0, 0);
    load_tiles(1, 1);

    float c[32][4];
    #pragma unroll
    for (int j = 0; j < 32; j++)
        #pragma unroll
        for (int i = 0; i < 4; i++) c[j][i] = 0.0f;

    for (int ki = 0; ki < 4; ki++) {
        const int buf = ki & 1;
        if (ki < 3) { CP_WAIT1(); } else { CP_WAIT0(); }
        __syncthreads();

        uint32_t a[4][4];
        #pragma unroll
        for (int kt = 0; kt < 4; kt++)
            ldsm4(a[kt][0], a[kt][1], a[kt][2], a[kt][3],
                  abase[buf] + (w * 16 + ar) * 128 + ((kt * 32 + ak) ^ axor));

        #pragma unroll
        for (int jp = 0; jp < 16; jp++) {
            #pragma unroll
            for (int kt = 0; kt < 4; kt++) {
                uint32_t r0, r1, r2, r3;
                ldsm4(r0, r1, r2, r3,
                      bbase[buf] + (jp * 16 + brow) * 128 + ((kt * 32 + bkb) ^ bxor));
                uint32_t blo[2] = { r0, r1 }, bhi[2] = { r2, r3 };
                mma16816(c[2 * jp],     a[kt], blo);
                mma16816(c[2 * jp + 1], a[kt], bhi);
            }
        }
        __syncthreads();

        if (ki + 2 < 4) load_tiles(ki + 2, buf);
    }

    const int r0g = m0 + w * 16 + g;
    float sum0 = 0.0f, sum1 = 0.0f;
    #pragma unroll
    for (int j = 0; j < 32; j++) {
        int n = 8 * j + 2 * tig;
        float2 x0 = *(const float2*)(X + (size_t)r0g * HH + n);
        float2 x1 = *(const float2*)(X + (size_t)(r0g + 8) * HH + n);
        float b0 = sgb[512 + n], b1 = sgb[512 + n + 1];
        c[j][0] += b0 + x0.x;
        c[j][1] += b1 + x0.y;
        c[j][2] += b0 + x1.x;
        c[j][3] += b1 + x1.y;
        sum0 += c[j][0] + c[j][1];
        sum1 += c[j][2] + c[j][3];
    }
    sum0 += __shfl_xor_sync(0xffffffffu, sum0, 1);
    sum0 += __shfl_xor_sync(0xffffffffu, sum0, 2);
    sum1 += __shfl_xor_sync(0xffffffffu, sum1, 1);
    sum1 += __shfl_xor_sync(0xffffffffu, sum1, 2);
    float mu0 = sum0 * (1.0f / 256.0f);
    float mu1 = sum1 * (1.0f / 256.0f);

    float vs0 = 0.0f, vs1 = 0.0f;
    #pragma unroll
    for (int j = 0; j < 32; j++) {
        float d0 = c[j][0] - mu0, d1 = c[j][1] - mu0;
        float d2 = c[j][2] - mu1, d3 = c[j][3] - mu1;
        vs0 += d0 * d0 + d1 * d1;
        vs1 += d2 * d2 + d3 * d3;
    }
    vs0 += __shfl_xor_sync(0xffffffffu, vs0, 1);
    vs0 += __shfl_xor_sync(0xffffffffu, vs0, 2);
    vs1 += __shfl_xor_sync(0xffffffffu, vs1, 1);
    vs1 += __shfl_xor_sync(0xffffffffu, vs1, 2);
    float inv0 = rsqrtf(vs0 * (1.0f / 256.0f) + 1e-12f);
    float inv1 = rsqrtf(vs1 * (1.0f / 256.0f) + 1e-12f);

    #pragma unroll
    for (int j = 0; j < 32; j++) {
        int n = 8 * j + 2 * tig;
        float ga0 = sgb[n], ga1 = sgb[n + 1];
        float be0 = sgb[256 + n], be1 = sgb[256 + n + 1];
        float2 o0, o1;
        o0.x = (c[j][0] - mu0) * inv0 * ga0 + be0;
        o0.y = (c[j][1] - mu0) * inv0 * ga1 + be1;
        o1.x = (c[j][2] - mu1) * inv1 * ga0 + be0;
        o1.y = (c[j][3] - mu1) * inv1 * ga1 + be1;
        *(float2*)(out + (size_t)r0g * HH + n)       = o0;
        *(float2*)(out + (size_t)(r0g + 8) * HH + n) = o1;
    }
}

// ---------------------------------------------------------------------------
extern "C" void kernel_launch(void* const* d_in, const int* in_sizes, int n_in,
                              void* d_out, int out_size)
{
    const float* X     = (const float*)d_in[0];
    const float* mask  = (const float*)d_in[1];
    const float* Wq    = (const float*)d_in[2];
    const float* bq    = (const float*)d_in[3];
    const float* Wk    = (const float*)d_in[4];
    const float* bk    = (const float*)d_in[5];
    const float* Wv    = (const float*)d_in[6];
    const float* bv    = (const float*)d_in[7];
    const float* Wo    = (const float*)d_in[8];
    const float* bo    = (const float*)d_in[9];
    const float* gamma = (const float*)d_in[10];
    const float* beta  = (const float*)d_in[11];
    float* out = (float*)d_out;

    cudaFuncSetAttribute(attn_kernel,
                         cudaFuncAttributeMaxDynamicSharedMemorySize, ATTN_SMEM);
    cudaFuncSetAttribute(qkv_kernel,
                         cudaFuncAttributeMaxDynamicSharedMemorySize, QKV_SMEM);
    cudaFuncSetAttribute(projln_kernel,
                         cudaFuncAttributeMaxDynamicSharedMemorySize, PLN_SMEM);

    cvt_x_kernel<<<MTOT * HH / 2048, 256>>>(X);
    cvt_w_kernel<<<dim3(HH / 32, HH / 32, 4), 256>>>(Wq, Wk, Wv, Wo);
    qkv_kernel<<<dim3(HH / 64, MTOT / 128, 3), 128, QKV_SMEM>>>(bq, bk, bv);
    attn_kernel<<<dim3(BB * NHH, SS / 128), 128, ATTN_SMEM>>>(mask);
    projln_kernel<<<MTOT / 64, 128, PLN_SMEM>>>(X, bo, gamma, beta, out);
}

// round 14
// speedup vs baseline: 1.7591x; 1.1989x over previous
#include <cuda_runtime.h>
#include <cuda_bf16.h>
#include <stdint.h>
#include <math.h>

#define BB   8
#define SS   2048
#define HH   256
#define NHH  4
#define HDD  64
#define MTOT (BB * SS)   // 16384

// ---------------------------------------------------------------------------
// Scratch (__device__ globals only).
// ---------------------------------------------------------------------------
__device__ __align__(128) __nv_bfloat16 g_Xb[MTOT * HH];       // X in bf16
__device__ __align__(128) __nv_bfloat16 g_Wtq[HH * HH];        // W^T bf16 [n][k]
__device__ __align__(128) __nv_bfloat16 g_Wtk[HH * HH];
__device__ __align__(128) __nv_bfloat16 g_Wtv[HH * HH];
__device__ __align__(128) __nv_bfloat16 g_Wto[HH * HH];
__device__ __align__(128) __nv_bfloat16 g_Qb[32 * SS * HDD];   // [bh][s][d]
__device__ __align__(128) __nv_bfloat16 g_Kb[32 * SS * HDD];   // [bh][s][d]
__device__ __align__(128) __nv_bfloat16 g_Vt[32 * HDD * SS];   // [bh][d][s]
__device__ __align__(128) __nv_bfloat16 g_ctxb[MTOT * HH];     // [m][h*64+d]

// ---------------------------------------------------------------------------
// Helpers
// ---------------------------------------------------------------------------
__device__ __forceinline__ uint32_t packbf(float lo, float hi) {
    uint32_t r;
    asm("cvt.rn.bf16x2.f32 %0, %1, %2;" : "=r"(r) : "f"(hi), "f"(lo));
    return r;
}

__device__ __forceinline__ void mma16816(float* c, const uint32_t* a, const uint32_t* b) {
    asm volatile(
        "mma.sync.aligned.m16n8k16.row.col.f32.bf16.bf16.f32 "
        "{%0,%1,%2,%3}, {%4,%5,%6,%7}, {%8,%9}, {%0,%1,%2,%3};\n"
        : "+f"(c[0]), "+f"(c[1]), "+f"(c[2]), "+f"(c[3])
        : "r"(a[0]), "r"(a[1]), "r"(a[2]), "r"(a[3]), "r"(b[0]), "r"(b[1]));
}

__device__ __forceinline__ uint32_t smem_u32(const void* p) {
    uint32_t a;
    asm("{ .reg .u64 t; cvta.to.shared.u64 t, %1; cvt.u32.u64 %0, t; }" : "=r"(a) : "l"(p));
    return a;
}

__device__ __forceinline__ void ldsm4(uint32_t& r0, uint32_t& r1, uint32_t& r2, uint32_t& r3,
                                      uint32_t addr) {
    asm volatile("ldmatrix.sync.aligned.m8n8.x4.shared.b16 {%0,%1,%2,%3}, [%4];"
                 : "=r"(r0), "=r"(r1), "=r"(r2), "=r"(r3) : "r"(addr));
}

__device__ __forceinline__ void cp16(uint32_t dst, const void* src) {
    asm volatile("cp.async.cg.shared.global [%0], [%1], 16;" :: "r"(dst), "l"(src));
}
#define CP_COMMIT() asm volatile("cp.async.commit_group;" ::: "memory")
#define CP_WAIT1()  asm volatile("cp.async.wait_group 1;" ::: "memory")
#define CP_WAIT0()  asm volatile("cp.async.wait_group 0;" ::: "memory")

// ---------------------------------------------------------------------------
// Kernel 0a: X fp32 -> bf16
// ---------------------------------------------------------------------------
__global__ __launch_bounds__(256) void cvt_x_kernel(const float* __restrict__ X)
{
    int idx = (blockIdx.x * 256 + threadIdx.x) * 8;
    float4 v0 = *(const float4*)(X + idx);
    float4 v1 = *(const float4*)(X + idx + 4);
    uint4 o;
    o.x = packbf(v0.x, v0.y);
    o.y = packbf(v0.z, v0.w);
    o.z = packbf(v1.x, v1.y);
    o.w = packbf(v1.z, v1.w);
    *(uint4*)&g_Xb[idx] = o;
}

// ---------------------------------------------------------------------------
// Kernel 0b: W fp32 [k][n] -> bf16 transposed [n][k]  (32x32 smem transpose)
// ---------------------------------------------------------------------------
__global__ __launch_bounds__(256) void cvt_w_kernel(
    const float* __restrict__ Wq, const float* __restrict__ Wk,
    const float* __restrict__ Wv, const float* __restrict__ Wo)
{
    __shared__ float sm[32][33];
    const float* W;  __nv_bfloat16* out;
    if (blockIdx.z == 0)      { W = Wq; out = g_Wtq; }
    else if (blockIdx.z == 1) { W = Wk; out = g_Wtk; }
    else if (blockIdx.z == 2) { W = Wv; out = g_Wtv; }
    else                      { W = Wo; out = g_Wto; }

    const int k0 = blockIdx.x * 32, n0 = blockIdx.y * 32;
    const int x = threadIdx.x & 31, y = threadIdx.x >> 5;
    #pragma unroll
    for (int i = 0; i < 4; i++) {
        int r = y + 8 * i;
        sm[r][x] = W[(k0 + r) * HH + n0 + x];
    }
    __syncthreads();
    #pragma unroll
    for (int i = 0; i < 4; i++) {
        int nr = y + 8 * i;
        out[(n0 + nr) * HH + k0 + x] = __float2bfloat16(sm[x][nr]);
    }
}

// ---------------------------------------------------------------------------
// Kernel 1: QKV projection (unchanged from R12/R13).
// ---------------------------------------------------------------------------
#define QSM_A0 0
#define QSM_A1 16384
#define QSM_B0 32768
#define QSM_B1 40960
#define QKV_SMEM 49152

__global__ __launch_bounds__(128) void qkv_kernel(
    const float* __restrict__ bq, const float* __restrict__ bk,
    const float* __restrict__ bv)
{
    extern __shared__ char qsm[];

    const int z = blockIdx.z;
    const __nv_bfloat16* Wt;  const float* bias;
    if (z == 0)      { Wt = g_Wtq; bias = bq; }
    else if (z == 1) { Wt = g_Wtk; bias = bk; }
    else             { Wt = g_Wtv; bias = bv; }

    const int t = threadIdx.x;
    const int w = t >> 5, lane = t & 31;
    const int g = lane >> 2, tig = lane & 3;
    const int m0 = blockIdx.y * 128, n0 = blockIdx.x * 64;

    const uint32_t smb = smem_u32(qsm);
    const uint32_t abase[2] = { smb + QSM_A0, smb + QSM_A1 };
    const uint32_t bbase[2] = { smb + QSM_B0, smb + QSM_B1 };

    const char* Xa = (const char*)g_Xb + (size_t)m0 * 512;
    const char* Wa = (const char*)Wt  + (size_t)n0 * 512;

    const int ar   = (lane & 7) + ((lane & 8) ? 8 : 0);
    const int ak   = (lane & 16) ? 16 : 0;
    const int axor = (lane & 7) * 16;
    const int brow = (lane & 7) | ((lane & 16) >> 1);
    const int bkb  = (lane & 8) ? 16 : 0;
    const int bxor = (brow & 7) * 16;

    auto load_tiles = [&](int ki, int buf) {
        const int kb = ki * 128;
        #pragma unroll
        for (int j = 0; j < 8; j++) {
            int c = t + 128 * j;
            int row = c >> 3, seg = c & 7;
            cp16(abase[buf] + row * 128 + ((seg * 16) ^ ((row & 7) * 16)),
                 Xa + (size_t)row * 512 + kb + seg * 16);
        }
        #pragma unroll
        for (int j = 0; j < 4; j++) {
            int c = t + 128 * j;
            int row = c >> 3, seg = c & 7;
            cp16(bbase[buf] + row * 128 + ((seg * 16) ^ ((row & 7) * 16)),
                 Wa + (size_t)row * 512 + kb + seg * 16);
        }
        CP_COMMIT();
    };

    load_tiles(0, 0);
    load_tiles(1, 1);

    float c[2][8][4];
    #pragma unroll
    for (int mt = 0; mt < 2; mt++)
        #pragma unroll
        for (int j = 0; j < 8; j++)
            #pragma unroll
            for (int i = 0; i < 4; i++) c[mt][j][i] = 0.0f;

    for (int ki = 0; ki < 4; ki++) {
        const int buf = ki & 1;
        if (ki < 3) { CP_WAIT1(); } else { CP_WAIT0(); }
        __syncthreads();

        uint32_t a[2][4][4];
        #pragma unroll
        for (int mt = 0; mt < 2; mt++)
            #pragma unroll
            for (int kt = 0; kt < 4; kt++)
                ldsm4(a[mt][kt][0], a[mt][kt][1], a[mt][kt][2], a[mt][kt][3],
                      abase[buf] + (w * 32 + mt * 16 + ar) * 128
                                 + ((kt * 32 + ak) ^ axor));

        #pragma unroll
        for (int jj = 0; jj < 4; jj++) {
            #pragma unroll
            for (int kt = 0; kt < 4; kt++) {
                uint32_t r0, r1, r2, r3;
                ldsm4(r0, r1, r2, r3,
                      bbase[buf] + (jj * 16 + brow) * 128 + ((kt * 32 + bkb) ^ bxor));
                uint32_t blo[2] = { r0, r1 }, bhi[2] = { r2, r3 };
                mma16816(c[0][2 * jj],     a[0][kt], blo);
                mma16816(c[0][2 * jj + 1], a[0][kt], bhi);
                mma16816(c[1][2 * jj],     a[1][kt], blo);
                mma16816(c[1][2 * jj + 1], a[1][kt], bhi);
            }
        }
        __syncthreads();

        if (ki + 2 < 4) load_tiles(ki + 2, buf);
    }

    const int head = blockIdx.x;
    if (z != 2) {
        __nv_bfloat16* out = (z == 0) ? g_Qb : g_Kb;
        #pragma unroll
        for (int mt = 0; mt < 2; mt++) {
            int r0 = m0 + w * 32 + mt * 16 + g;
            #pragma unroll
            for (int half = 0; half < 2; half++) {
                int m  = r0 + half * 8;
                int b_ = m >> 11;
                int s_ = m & (SS - 1);
                int bh = b_ * NHH + head;
                #pragma unroll
                for (int j = 0; j < 8; j++) {
                    int d = 8 * j + 2 * tig;
                    float v0 = c[mt][j][half * 2 + 0] + bias[n0 + d];
                    float v1 = c[mt][j][half * 2 + 1] + bias[n0 + d + 1];
                    *(uint32_t*)&out[(bh * SS + s_) * HDD + d] = packbf(v0, v1);
                }
            }
        }
    } else {
        __nv_bfloat16* Ts = (__nv_bfloat16*)qsm;
        #pragma unroll
        for (int mt = 0; mt < 2; mt++) {
            #pragma unroll
            for (int half = 0; half < 2; half++) {
                int sl = w * 32 + mt * 16 + g + half * 8;
                #pragma unroll
                for (int j = 0; j < 8; j++) {
                    int d = 8 * j + 2 * tig;
                    float v0 = c[mt][j][half * 2 + 0] + bias[n0 + d];
                    float v1 = c[mt][j][half * 2 + 1] + bias[n0 + d + 1];
                    Ts[d * 136 + sl]       = __float2bfloat16(v0);
                    Ts[(d + 1) * 136 + sl] = __float2bfloat16(v1);
                }
            }
        }
        __syncthreads();
        int d = t >> 1, half = t & 1;
        int b_ = m0 >> 11;
        int s0 = m0 & (SS - 1);
        int bh = b_ * NHH + head;
        const uint4* src = (const uint4*)&Ts[d * 136 + half * 64];
        uint4* dst = (uint4*)&g_Vt[((size_t)bh * HDD + d) * SS + s0 + half * 64];
        #pragma unroll
        for (int i = 0; i < 8; i++) dst[i] = src[i];
    }
}

// ---------------------------------------------------------------------------
// Kernel 2: flash attention — BQ=64, 4 warps, 16 q-rows/warp, 3 CTAs/SM.
// Same pipeline/softmax/layouts as R13, mt-dimension removed.
// Dynamic smem 67584 B: K0@0 K1@8192 V0@16384 V1@24576,
// M0@32768 M1@50176 (64 rows x 68 floats each).
// ---------------------------------------------------------------------------
#define NIT 32            // SS / 64
#define SM_K0   0
#define SM_K1   8192
#define SM_V0   16384
#define SM_V1   24576
#define SM_M0   32768
#define SM_M1   50176
#define MPITCH  68
#define ATTN_SMEM 67584

__global__ __launch_bounds__(128, 3) void attn_kernel(const float* __restrict__ mask)
{
    extern __shared__ char dynsm[];

    const int t = threadIdx.x;
    const int w = t >> 5, lane = t & 31;
    const int g = lane >> 2, tig = lane & 3;
    const int bh = blockIdx.x;
    const int qb = blockIdx.y;            // 0..31, 64-row q-tiles
    const int b_ = bh >> 2;
    const int h_ = bh & 3;

    const uint32_t smb = smem_u32(dynsm);

    const __nv_bfloat16* Qg = g_Qb + (size_t)bh * SS * HDD;
    const char* Kg = (const char*)(g_Kb + (size_t)bh * SS * HDD);
    const char* Vg = (const char*)(g_Vt + (size_t)bh * HDD * SS);
    const float* Mb = mask + (size_t)b_ * SS * SS + (size_t)(qb * 64) * SS;

    // ldmatrix addressing (B-frags for both S and PV loops)
    const int lrow = (lane & 7) | ((lane & 16) >> 1);
    const int lkb  = (lane & 8) ? 16 : 0;
    const int lxor = (lrow & 7) * 16;
    const int lbase = lrow * 128;

    // Q A-fragments: one 16-row m-tile per warp
    const int qrow = qb * 64 + w * 16 + g;
    uint32_t aq[4][4];
    {
        const __nv_bfloat16* r0 = Qg + (size_t)qrow * HDD;
        const __nv_bfloat16* r1 = r0 + 8 * HDD;
        #pragma unroll
        for (int kt = 0; kt < 4; kt++) {
            aq[kt][0] = *(const uint32_t*)(r0 + kt * 16 + 2 * tig);
            aq[kt][1] = *(const uint32_t*)(r1 + kt * 16 + 2 * tig);
            aq[kt][2] = *(const uint32_t*)(r0 + kt * 16 + 2 * tig + 8);
            aq[kt][3] = *(const uint32_t*)(r1 + kt * 16 + 2 * tig + 8);
        }
    }

    // Tile loader: K/V 64x64 tiles + 64x64 mask tile, addressing inline.
    auto load_tiles = [&](int it, int buf) {
        const uint32_t kb = smb + (buf ? SM_K1 : SM_K0);
        const uint32_t vb = smb + (buf ? SM_V1 : SM_V0);
        const uint32_t mb = smb + (buf ? SM_M1 : SM_M0);
        const char* Ks = Kg + (size_t)it * 64 * 128;
        #pragma unroll
        for (int jc = 0; jc < 4; jc++) {
            int c = t + 128 * jc;
            int row = c >> 3, seg = c & 7;
            uint32_t dst = row * 128 + ((seg * 16) ^ ((row & 7) * 16));
            cp16(kb + dst, Ks + row * 128 + seg * 16);
            cp16(vb + dst, Vg + (size_t)row * (SS * 2) + it * 128 + seg * 16);
        }
        #pragma unroll
        for (int jm = 0; jm < 8; jm++) {
            int c = t + 128 * jm;
            int row = c >> 4, seg = c & 15;
            cp16(mb + row * (MPITCH * 4) + seg * 16,
                 (const char*)(Mb + (size_t)row * SS + it * 64) + seg * 16);
        }
        CP_COMMIT();
    };

    load_tiles(0, 0);
    load_tiles(1, 1);

    float o[8][4];
    #pragma unroll
    for (int j = 0; j < 8; j++)
        #pragma unroll
        for (int i = 0; i < 4; i++) o[j][i] = 0.0f;
    float lacc[2] = {0.0f, 0.0f};

    for (int i = 0; i < NIT; i++) {
        const int buf = i & 1;
        const uint32_t kb = smb + (buf ? SM_K1 : SM_K0);
        const uint32_t vb = smb + (buf ? SM_V1 : SM_V0);
        const float* msm = (const float*)(dynsm + (buf ? SM_M1 : SM_M0));

        if (i < NIT - 1) { CP_WAIT1(); } else { CP_WAIT0(); }
        __syncthreads();

        // ---- S = Q @ K^T (16 x 64 per warp) ----
        float c[8][4];
        #pragma unroll
        for (int j = 0; j < 8; j++)
            #pragma unroll
            for (int q = 0; q < 4; q++) c[j][q] = 0.0f;

        #pragma unroll
        for (int jj = 0; jj < 4; jj++) {
            #pragma unroll
            for (int kt = 0; kt < 4; kt++) {
                uint32_t r0, r1, r2, r3;
                ldsm4(r0, r1, r2, r3,
                      kb + jj * 2048 + lbase + ((kt * 32 + lkb) ^ lxor));
                uint32_t blo[2] = { r0, r1 }, bhi[2] = { r2, r3 };
                mma16816(c[2 * jj],     aq[kt], blo);
                mma16816(c[2 * jj + 1], aq[kt], bhi);
            }
        }

        // ---- softmax (no max): p = exp(s/8 + mask), mask from SMEM ----
        uint32_t pa[4][4];
        {
            const float* mp0 = msm + (w * 16 + g) * MPITCH + 2 * tig;
            const float* mp1 = mp0 + 8 * MPITCH;
            #pragma unroll
            for (int j = 0; j < 8; j++) {
                float2 mk0 = *(const float2*)(mp0 + 8 * j);
                float2 mk1 = *(const float2*)(mp1 + 8 * j);
                float p0 = __expf(fmaf(c[j][0], 0.125f, mk0.x));
                float p1 = __expf(fmaf(c[j][1], 0.125f, mk0.y));
                float p2 = __expf(fmaf(c[j][2], 0.125f, mk1.x));
                float p3 = __expf(fmaf(c[j][3], 0.125f, mk1.y));
                lacc[0] += p0 + p1;
                lacc[1] += p2 + p3;
                int kt = j >> 1, hi = (j & 1) * 2;
                pa[kt][hi + 0] = packbf(p0, p1);
                pa[kt][hi + 1] = packbf(p2, p3);
            }
        }

        // ---- O += P @ V (V tile is [d][kv], non-trans ldmatrix) ----
        #pragma unroll
        for (int jj = 0; jj < 4; jj++) {
            #pragma unroll
            for (int kt = 0; kt < 4; kt++) {
                uint32_t r0, r1, r2, r3;
                ldsm4(r0, r1, r2, r3,
                      vb + jj * 2048 + lbase + ((kt * 32 + lkb) ^ lxor));
                uint32_t blo[2] = { r0, r1 }, bhi[2] = { r2, r3 };
                mma16816(o[2 * jj],     pa[kt], blo);
                mma16816(o[2 * jj + 1], pa[kt], bhi);
            }
        }

        __syncthreads();

        if (i + 2 < NIT) load_tiles(i + 2, buf);
    }

    // ---- final: reduce l across 4 lanes of each row group, write ctx ----
    #pragma unroll
    for (int h = 0; h < 2; h++) {
        float v = lacc[h];
        v += __shfl_xor_sync(0xffffffffu, v, 1);
        v += __shfl_xor_sync(0xffffffffu, v, 2);
        lacc[h] = 1.0f / v;
    }

    {
        __nv_bfloat16* c0 = g_ctxb + ((size_t)b_ * SS + qrow) * HH + h_ * HDD;
        __nv_bfloat16* c1 = c0 + 8 * HH;
        #pragma unroll
        for (int j = 0; j < 8; j++) {
            int d = 8 * j + 2 * tig;
            *(uint32_t*)(c0 + d) = packbf(o[j][0] * lacc[0], o[j][1] * lacc[0]);
            *(uint32_t*)(c1 + d) = packbf(o[j][2] * lacc[1], o[j][3] * lacc[1]);
        }
    }
}

// ---------------------------------------------------------------------------
// Kernel 3: out projection + residual + LayerNorm fused (unchanged from R12).
// ---------------------------------------------------------------------------
#define PSM_A0 0
#define PSM_A1 8192
#define PSM_B0 16384
#define PSM_B1 49152
#define PLN_SMEM 81920

__global__ __launch_bounds__(128) void projln_kernel(
    const float* __restrict__ X,
    const float* __restrict__ bo,
    const float* __restrict__ gamma, const float* __restrict__ beta,
    float* __restrict__ out)
{
    extern __shared__ char psm[];
    __shared__ float sgb[256 * 3];

    const int t = threadIdx.x;
    const int w = t >> 5, lane = t & 31;
    const int g = lane >> 2, tig = lane & 3;
    const int m0 = blockIdx.x * 64;

    const uint32_t smb = smem_u32(psm);
    const uint32_t abase[2] = { smb + PSM_A0, smb + PSM_A1 };
    const uint32_t bbase[2] = { smb + PSM_B0, smb + PSM_B1 };

    const char* Ca = (const char*)g_ctxb + (size_t)m0 * 512;
    const char* Wa = (const char*)g_Wto;

    const int ar   = (lane & 7) + ((lane & 8) ? 8 : 0);
    const int ak   = (lane & 16) ? 16 : 0;
    const int axor = (lane & 7) * 16;
    const int brow = (lane & 7) | ((lane & 16) >> 1);
    const int bkb  = (lane & 8) ? 16 : 0;
    const int bxor = (brow & 7) * 16;

    sgb[t]             = gamma[t];
    sgb[t + 128]       = gamma[t + 128];
    sgb[256 + t]       = beta[t];
    sgb[256 + t + 128] = beta[t + 128];
    sgb[512 + t]       = bo[t];
    sgb[512 + t + 128] = bo[t + 128];

    auto load_tiles = [&](int ki, int buf) {
        const int kb = ki * 128;
        #pragma unroll
        for (int j = 0; j < 4; j++) {
            int c = t + 128 * j;
            int row = c >> 3, seg = c & 7;
            cp16(abase[buf] + row * 128 + ((seg * 16) ^ ((row & 7) * 16)),
                 Ca + (size_t)row * 512 + kb + seg * 16);
        }
        #pragma unroll
        for (int j = 0; j < 16; j++) {
            int c = t + 128 * j;
            int row = c >> 3, seg = c & 7;
            cp16(bbase[buf] + row * 128 + ((seg * 16) ^ ((row & 7) * 16)),
                 Wa + (size_t)row * 512 + kb + seg * 16);
        }
        CP_COMMIT();
    };

    load_tiles(0, 0);
    load_tiles(1, 1);

    float c[32][4];
    #pragma unroll
    for (int j = 0; j < 32; j++)
        #pragma unroll
        for (int i = 0; i < 4; i++) c[j][i] = 0.0f;

    for (int ki = 0; ki < 4; ki++) {
        const int buf = ki & 1;
        if (ki < 3) { CP_WAIT1(); } else { CP_WAIT0(); }
        __syncthreads();

        uint32_t a[4][4];
        #pragma unroll
        for (int kt = 0; kt < 4; kt++)
            ldsm4(a[kt][0], a[kt][1], a[kt][2], a[kt][3],
                  abase[buf] + (w * 16 + ar) * 128 + ((kt * 32 + ak) ^ axor));

        #pragma unroll
        for (int jp = 0; jp < 16; jp++) {
            #pragma unroll
            for (int kt = 0; kt < 4; kt++) {
                uint32_t r0, r1, r2, r3;
                ldsm4(r0, r1, r2, r3,
                      bbase[buf] + (jp * 16 + brow) * 128 + ((kt * 32 + bkb) ^ bxor));
                uint32_t blo[2] = { r0, r1 }, bhi[2] = { r2, r3 };
                mma16816(c[2 * jp],     a[kt], blo);
                mma16816(c[2 * jp + 1], a[kt], bhi);
            }
        }
        __syncthreads();

        if (ki + 2 < 4) load_tiles(ki + 2, buf);
    }

    const int r0g = m0 + w * 16 + g;
    float sum0 = 0.0f, sum1 = 0.0f;
    #pragma unroll
    for (int j = 0; j < 32; j++) {
        int n = 8 * j + 2 * tig;
        float2 x0 = *(const float2*)(X + (size_t)r0g * HH + n);
        float2 x1 = *(const float2*)(X + (size_t)(r0g + 8) * HH + n);
        float b0 = sgb[512 + n], b1 = sgb[512 + n + 1];
        c[j][0] += b0 + x0.x;
        c[j][1] += b1 + x0.y;
        c[j][2] += b0 + x1.x;
        c[j][3] += b1 + x1.y;
        sum0 += c[j][0] + c[j][1];
        sum1 += c[j][2] + c[j][3];
    }
    sum0 += __shfl_xor_sync(0xffffffffu, sum0, 1);
    sum0 += __shfl_xor_sync(0xffffffffu, sum0, 2);
    sum1 += __shfl_xor_sync(0xffffffffu, sum1, 1);
    sum1 += __shfl_xor_sync(0xffffffffu, sum1, 2);
    float mu0 = sum0 * (1.0f / 256.0f);
    float mu1 = sum1 * (1.0f / 256.0f);

    float vs0 = 0.0f, vs1 = 0.0f;
    #pragma unroll
    for (int j = 0; j < 32; j++) {
        float d0 = c[j][0] - mu0, d1 = c[j][1] - mu0;
        float d2 = c[j][2] - mu1, d3 = c[j][3] - mu1;
        vs0 += d0 * d0 + d1 * d1;
        vs1 += d2 * d2 + d3 * d3;
    }
    vs0 += __shfl_xor_sync(0xffffffffu, vs0, 1);
    vs0 += __shfl_xor_sync(0xffffffffu, vs0, 2);
    vs1 += __shfl_xor_sync(0xffffffffu, vs1, 1);
    vs1 += __shfl_xor_sync(0xffffffffu, vs1, 2);
    float inv0 = rsqrtf(vs0 * (1.0f / 256.0f) + 1e-12f);
    float inv1 = rsqrtf(vs1 * (1.0f / 256.0f) + 1e-12f);

    #pragma unroll
    for (int j = 0; j < 32; j++) {
        int n = 8 * j + 2 * tig;
        float ga0 = sgb[n], ga1 = sgb[n + 1];
        float be0 = sgb[256 + n], be1 = sgb[256 + n + 1];
        float2 o0, o1;
        o0.x = (c[j][0] - mu0) * inv0 * ga0 + be0;
        o0.y = (c[j][1] - mu0) * inv0 * ga1 + be1;
        o1.x = (c[j][2] - mu1) * inv1 * ga0 + be0;
        o1.y = (c[j][3] - mu1) * inv1 * ga1 + be1;
        *(float2*)(out + (size_t)r0g * HH + n)       = o0;
        *(float2*)(out + (size_t)(r0g + 8) * HH + n) = o1;
    }
}

// ---------------------------------------------------------------------------
extern "C" void kernel_launch(void* const* d_in, const int* in_sizes, int n_in,
                              void* d_out, int out_size)
{
    const float* X     = (const float*)d_in[0];
    const float* mask  = (const float*)d_in[1];
    const float* Wq    = (const float*)d_in[2];
    const float* bq    = (const float*)d_in[3];
    const float* Wk    = (const float*)d_in[4];
    const float* bk    = (const float*)d_in[5];
    const float* Wv    = (const float*)d_in[6];
    const float* bv    = (const float*)d_in[7];
    const float* Wo    = (const float*)d_in[8];
    const float* bo    = (const float*)d_in[9];
    const float* gamma = (const float*)d_in[10];
    const float* beta  = (const float*)d_in[11];
    float* out = (float*)d_out;

    cudaFuncSetAttribute(attn_kernel,
                         cudaFuncAttributeMaxDynamicSharedMemorySize, ATTN_SMEM);
    cudaFuncSetAttribute(qkv_kernel,
                         cudaFuncAttributeMaxDynamicSharedMemorySize, QKV_SMEM);
    cudaFuncSetAttribute(projln_kernel,
                         cudaFuncAttributeMaxDynamicSharedMemorySize, PLN_SMEM);

    cvt_x_kernel<<<MTOT * HH / 2048, 256>>>(X);
    cvt_w_kernel<<<dim3(HH / 32, HH / 32, 4), 256>>>(Wq, Wk, Wv, Wo);
    qkv_kernel<<<dim3(HH / 64, MTOT / 128, 3), 128, QKV_SMEM>>>(bq, bk, bv);
    attn_kernel<<<dim3(BB * NHH, SS / 64), 128, ATTN_SMEM>>>(mask);
    projln_kernel<<<MTOT / 64, 128, PLN_SMEM>>>(X, bo, gamma, beta, out);
}